// round 11
// baseline (speedup 1.0000x reference)
#include <cuda_runtime.h>
#include <cuda_fp16.h>
#include <math.h>

// ---------------- problem constants ----------------
#define Bq   16
#define LQn  512
#define LKVn 512
#define Dm   768
#define Hn   12
#define HDn  64
#define HIDn 3072
#define NTOK (Bq*LQn)          // 8192

// ---------------- scratch (device globals, plain fp16) ----------------
__device__ __align__(16) __half g_x   [NTOK*Dm];
__device__ __align__(16) __half g_xkv [NTOK*Dm];
__device__ __align__(16) __half g_qkv [NTOK*3*Dm];
__device__ __align__(16) __half g_attn[NTOK*Dm];
__device__ __align__(16) __half g_qh  [NTOK*Dm];
__device__ __align__(16) __half g_kvp [NTOK*2*Dm];
__device__ float  g_q1  [NTOK*Dm];
__device__ float  g_q2  [NTOK*Dm];
__device__ __align__(16) __half g_hid [NTOK*HIDn];
// converted weights
__device__ __align__(16) __half g_wqkv [3*Dm*Dm];
__device__ __align__(16) __half g_wsa  [Dm*Dm];
__device__ __align__(16) __half g_wcaq [Dm*Dm];
__device__ __align__(16) __half g_wcakv[2*Dm*Dm];
__device__ __align__(16) __half g_wcap [Dm*Dm];
__device__ __align__(16) __half g_wfc1 [HIDn*Dm];
__device__ __align__(16) __half g_wfc2 [Dm*HIDn];

// ---------------- helpers ----------------
__device__ __forceinline__ float warp_sum(float v){
#pragma unroll
    for (int o = 16; o > 0; o >>= 1) v += __shfl_xor_sync(0xffffffffu, v, o);
    return v;
}

__device__ __forceinline__ void mma16816(float* c, const unsigned* a, const unsigned* b){
    asm volatile(
        "mma.sync.aligned.m16n8k16.row.col.f32.f16.f16.f32 "
        "{%0,%1,%2,%3},{%4,%5,%6,%7},{%8,%9},{%0,%1,%2,%3};"
        : "+f"(c[0]), "+f"(c[1]), "+f"(c[2]), "+f"(c[3])
        : "r"(a[0]), "r"(a[1]), "r"(a[2]), "r"(a[3]), "r"(b[0]), "r"(b[1]));
}

__device__ __forceinline__ void cp16(void* smem_dst, const void* gsrc){
    unsigned s = (unsigned)__cvta_generic_to_shared(smem_dst);
    asm volatile("cp.async.cg.shared.global [%0], [%1], 16;\n" :: "r"(s), "l"(gsrc));
}
#define CP_COMMIT()  asm volatile("cp.async.commit_group;\n" ::: "memory")
#define CP_WAIT_1()  asm volatile("cp.async.wait_group 1;\n" ::: "memory")
#define CP_WAIT_0()  asm volatile("cp.async.wait_group 0;\n" ::: "memory")

// pack two fp32 into f16x2 register (low16 = p0)
__device__ __forceinline__ unsigned packf2(float p0, float p1){
    unsigned r;
    asm("cvt.rn.f16x2.f32 %0, %1, %2;" : "=r"(r) : "f"(p1), "f"(p0));
    return r;
}

// ---------------- merged weight conversion (blockIdx.y = segment) ----------------
struct CvtArgs {
    const float* s[7];
    __half*      d[7];
    int          n[7];
};
__global__ void cvt_all(CvtArgs a){
    const int seg = blockIdx.y;
    const int i = blockIdx.x * 256 + threadIdx.x;
    if (i < a.n[seg]) a.d[seg][i] = __float2half_rn(a.s[seg][i]);
}

// ---------------- LayerNorm -> fp16 ----------------
__global__ void ln_kernel(const float* __restrict__ x, const float* __restrict__ g,
                          const float* __restrict__ b, __half* __restrict__ y)
{
    __shared__ float sh[8];
    const long row = blockIdx.x;
    const float* xr = x + row * Dm;
    __half* yr = y + row * Dm;
    const int tid = threadIdx.x;
    const int w = tid >> 5, l = tid & 31;

    float v0 = xr[tid], v1 = xr[tid + 256], v2 = xr[tid + 512];

    float s = warp_sum(v0 + v1 + v2);
    if (l == 0) sh[w] = s;
    __syncthreads();
    if (w == 0) { float t = (l < 8) ? sh[l] : 0.f; t = warp_sum(t); if (l == 0) sh[0] = t; }
    __syncthreads();
    const float mean = sh[0] * (1.f / 768.f);
    __syncthreads();

    const float d0 = v0 - mean, d1 = v1 - mean, d2 = v2 - mean;
    float s2 = warp_sum(d0*d0 + d1*d1 + d2*d2);
    if (l == 0) sh[w] = s2;
    __syncthreads();
    if (w == 0) { float t = (l < 8) ? sh[l] : 0.f; t = warp_sum(t); if (l == 0) sh[0] = t; }
    __syncthreads();
    const float inv = rsqrtf(sh[0] * (1.f / 768.f) + 1e-5f);

    yr[tid]       = __float2half_rn(d0 * inv * g[tid]       + b[tid]);
    yr[tid + 256] = __float2half_rn(d1 * inv * g[tid + 256] + b[tid + 256]);
    yr[tid + 512] = __float2half_rn(d2 * inv * g[tid + 512] + b[tid + 512]);
}

// ---------------- fused flash attention (fp16 in/out, 128 Q-rows x 512 keys) ----------------
#define QS_ST 72
#define KS_ST 72
#define VS_ST 72
#define Q_TILE (128*QS_ST)   // halves
#define K_TILE (128*KS_ST)
#define V_TILE (128*VS_ST)
#define FLASH_SMEM ((Q_TILE + 2*K_TILE + 2*V_TILE) * 2)   // 92160 B

__global__ void __launch_bounds__(256, 1)
flash_kernel(const __half* __restrict__ Q, int ldq, long Qb,
             const __half* __restrict__ K, int ldk, long Kb,
             const __half* __restrict__ V, int ldv, long Vb,
             __half* __restrict__ O, int ldo, long Ob)
{
    extern __shared__ __half smh[];
    __half* Qs = smh;
    __half* Ks = smh + Q_TILE;
    __half* Vs = smh + Q_TILE + 2*K_TILE;

    const int tid  = threadIdx.x;
    const int wid  = tid >> 5, lane = tid & 31;
    const int g    = lane >> 2, t2 = (lane & 3) * 2;
    const int m0   = blockIdx.x * 128;
    const int wrow = wid * 16;

    {
        const int z = blockIdx.y;
        const int bb = z / Hn, hh = z - bb * Hn;
        Q += (long)bb * Qb + hh * 64;
        K += (long)bb * Kb + hh * 64;
        V += (long)bb * Vb + hh * 64;
        O += (long)bb * Ob + hh * 64;
    }

    auto loadQ = [&](){
#pragma unroll
        for (int idx = tid; idx < 1024; idx += 256) {
            const int r = idx >> 3, c = idx & 7;
            cp16(&Qs[r * QS_ST + c * 8], Q + (long)(m0 + r) * ldq + c * 8);
        }
    };
    auto loadK = [&](int kt, int s){
        __half* dst = Ks + s * K_TILE;
#pragma unroll
        for (int idx = tid; idx < 1024; idx += 256) {
            const int r = idx >> 3, c = idx & 7;
            cp16(&dst[r * KS_ST + c * 8], K + (long)(kt * 128 + r) * ldk + c * 8);
        }
    };
    auto loadV = [&](int kt, int s){
        __half* dst = Vs + s * V_TILE;
#pragma unroll
        for (int idx = tid; idx < 1024; idx += 256) {
            const int r = idx >> 3, c = idx & 7;
            cp16(&dst[r * VS_ST + c * 8], V + (long)(kt * 128 + r) * ldv + c * 8);
        }
    };

    float o[8][4];
#pragma unroll
    for (int i = 0; i < 8; i++)
#pragma unroll
        for (int j = 0; j < 4; j++) o[i][j] = 0.f;
    float m_a = -1e30f, m_b = -1e30f, l_a = 0.f, l_b = 0.f;

    loadQ(); loadK(0, 0); loadV(0, 0); CP_COMMIT();
    loadK(1, 1); loadV(1, 1); CP_COMMIT();

    for (int it = 0; it < 4; it++) {
        if (it >= 1) {
            __syncthreads();
            if (it + 1 < 4) { loadK(it + 1, (it + 1) & 1); loadV(it + 1, (it + 1) & 1); CP_COMMIT(); }
        }
        if (it + 1 < 4) CP_WAIT_1(); else CP_WAIT_0();
        __syncthreads();

        const __half* Kc = Ks + (it & 1) * K_TILE;
        const __half* Vc = Vs + (it & 1) * V_TILE;

        // ---- S = Q K^T ----
        float s[16][4];
#pragma unroll
        for (int nt = 0; nt < 16; nt++)
#pragma unroll
            for (int c = 0; c < 4; c++) s[nt][c] = 0.f;

#pragma unroll
        for (int kk = 0; kk < 64; kk += 16) {
            const int r = wrow + g;
            unsigned ra[4];
            ra[0] = *(const unsigned*)&Qs[r       * QS_ST + kk + t2];
            ra[1] = *(const unsigned*)&Qs[(r + 8) * QS_ST + kk + t2];
            ra[2] = *(const unsigned*)&Qs[r       * QS_ST + kk + t2 + 8];
            ra[3] = *(const unsigned*)&Qs[(r + 8) * QS_ST + kk + t2 + 8];
#pragma unroll
            for (int nt = 0; nt < 16; nt++) {
                const int kr = nt * 8 + g;
                unsigned rb[2];
                rb[0] = *(const unsigned*)&Kc[kr * KS_ST + kk + t2];
                rb[1] = *(const unsigned*)&Kc[kr * KS_ST + kk + t2 + 8];
                mma16816(s[nt], ra, rb);
            }
        }

        // ---- online softmax (scale 1/8 folded) ----
        float mx_a = -1e30f, mx_b = -1e30f;
#pragma unroll
        for (int nt = 0; nt < 16; nt++) {
#pragma unroll
            for (int c = 0; c < 4; c++) s[nt][c] *= 0.125f;
            mx_a = fmaxf(mx_a, fmaxf(s[nt][0], s[nt][1]));
            mx_b = fmaxf(mx_b, fmaxf(s[nt][2], s[nt][3]));
        }
        mx_a = fmaxf(mx_a, __shfl_xor_sync(0xffffffffu, mx_a, 1));
        mx_a = fmaxf(mx_a, __shfl_xor_sync(0xffffffffu, mx_a, 2));
        mx_b = fmaxf(mx_b, __shfl_xor_sync(0xffffffffu, mx_b, 1));
        mx_b = fmaxf(mx_b, __shfl_xor_sync(0xffffffffu, mx_b, 2));

        const float nm_a = fmaxf(m_a, mx_a);
        const float nm_b = fmaxf(m_b, mx_b);
        const float sc_a = __expf(m_a - nm_a);
        const float sc_b = __expf(m_b - nm_b);
        m_a = nm_a; m_b = nm_b;
        l_a *= sc_a; l_b *= sc_b;
#pragma unroll
        for (int nt = 0; nt < 8; nt++) {
            o[nt][0] *= sc_a; o[nt][1] *= sc_a;
            o[nt][2] *= sc_b; o[nt][3] *= sc_b;
        }
        float sum_a = 0.f, sum_b = 0.f;
#pragma unroll
        for (int nt = 0; nt < 16; nt++) {
            s[nt][0] = __expf(s[nt][0] - nm_a);
            s[nt][1] = __expf(s[nt][1] - nm_a);
            s[nt][2] = __expf(s[nt][2] - nm_b);
            s[nt][3] = __expf(s[nt][3] - nm_b);
            sum_a += s[nt][0] + s[nt][1];
            sum_b += s[nt][2] + s[nt][3];
        }
        l_a += sum_a; l_b += sum_b;

        // ---- O += P V ----
        const unsigned short* Vu = (const unsigned short*)Vc;
#pragma unroll
        for (int ks = 0; ks < 8; ks++) {
            unsigned ra[4];
            ra[0] = packf2(s[2*ks  ][0], s[2*ks  ][1]);
            ra[1] = packf2(s[2*ks  ][2], s[2*ks  ][3]);
            ra[2] = packf2(s[2*ks+1][0], s[2*ks+1][1]);
            ra[3] = packf2(s[2*ks+1][2], s[2*ks+1][3]);
            const int r0 = ks * 16 + t2;
#pragma unroll
            for (int nt = 0; nt < 8; nt++) {
                const int n = nt * 8 + g;
                unsigned b0 = (unsigned)Vu[(r0    ) * VS_ST + n]
                            | ((unsigned)Vu[(r0 + 1) * VS_ST + n] << 16);
                unsigned b1 = (unsigned)Vu[(r0 + 8) * VS_ST + n]
                            | ((unsigned)Vu[(r0 + 9) * VS_ST + n] << 16);
                unsigned rb[2] = {b0, b1};
                mma16816(o[nt], ra, rb);
            }
        }
    }

    l_a += __shfl_xor_sync(0xffffffffu, l_a, 1);
    l_a += __shfl_xor_sync(0xffffffffu, l_a, 2);
    l_b += __shfl_xor_sync(0xffffffffu, l_b, 1);
    l_b += __shfl_xor_sync(0xffffffffu, l_b, 2);
    const float inv_a = 1.f / l_a;
    const float inv_b = 1.f / l_b;

    const int row_a = m0 + wrow + g;
    const int row_b = row_a + 8;
#pragma unroll
    for (int nt = 0; nt < 8; nt++) {
        const int col = nt * 8 + t2;
        *(unsigned*)&O[(long)row_a * ldo + col] = packf2(o[nt][0] * inv_a, o[nt][1] * inv_a);
        *(unsigned*)&O[(long)row_b * ldo + col] = packf2(o[nt][2] * inv_b, o[nt][3] * inv_b);
    }
}

// ---------------- fp16 tensor-core GEMM, 2-stage cp.async, 4 CTAs/SM ----------------
// C[m,n] = sum_k A[m,k]*B[n,k]. ACT==1: exact GELU. OUTH: fp16 out else fp32 (+bias/resid).
template<int BM, int BN, int BK, int WM, int WN, int ACT, bool OUTH>
__global__ void __launch_bounds__(256, 4)
mma_gemm(const __half* __restrict__ A, int lda,
         const __half* __restrict__ B, int ldb,
         void* __restrict__ Cv, int ldc,
         int K,
         const float* __restrict__ bias,
         const float* __restrict__ resid, int ldr)
{
    constexpr int AST   = BK + 8;                      // 40 halves (80 B)
    constexpr int BST   = BK + 8;
    constexpr int A_TILE = BM * AST;                   // halves
    constexpr int B_TILE = BN * BST;
    constexpr int STAGE  = A_TILE + B_TILE;
    constexpr int NWN = BN / WN;
    constexpr int MT  = WM / 16;
    constexpr int NT  = WN / 8;

    extern __shared__ __half smh[];

    const int tid = threadIdx.x;
    const int wid = tid >> 5, lane = tid & 31;
    const int wm = wid / NWN, wn = wid % NWN;
    const int g  = lane >> 2, t2 = (lane & 3) * 2;

    const int m0 = blockIdx.y * BM, n0 = blockIdx.x * BN;

    float acc[MT][NT][4];
#pragma unroll
    for (int i = 0; i < MT; i++)
#pragma unroll
        for (int j = 0; j < NT; j++)
#pragma unroll
            for (int c = 0; c < 4; c++) acc[i][j][c] = 0.f;

    auto load_tiles = [&](int k0, int s){
        __half* Ad = smh + s * STAGE;
        __half* Bd = Ad + A_TILE;
        constexpr int ACH = BM * BK / 8;               // 16B chunks
#pragma unroll
        for (int idx = tid; idx < ACH; idx += 256) {
            const int r = idx / (BK / 8), c = idx % (BK / 8);
            cp16(&Ad[r * AST + c * 8], A + (long)(m0 + r) * lda + k0 + c * 8);
        }
        constexpr int BCH = BN * BK / 8;
#pragma unroll
        for (int idx = tid; idx < BCH; idx += 256) {
            const int r = idx / (BK / 8), c = idx % (BK / 8);
            cp16(&Bd[r * BST + c * 8], B + (long)(n0 + r) * ldb + k0 + c * 8);
        }
    };

    const int iters = K / BK;
    load_tiles(0, 0);
    CP_COMMIT();

    for (int it = 0; it < iters; it++) {
        if (it + 1 < iters) {
            load_tiles((it + 1) * BK, (it + 1) & 1);
            CP_COMMIT();
            CP_WAIT_1();
        } else {
            CP_WAIT_0();
        }
        __syncthreads();

        const __half* Ac = smh + (it & 1) * STAGE;
        const __half* Bc = Ac + A_TILE;

#pragma unroll
        for (int kk = 0; kk < BK; kk += 16) {
            unsigned rb[NT][2];
#pragma unroll
            for (int nt = 0; nt < NT; nt++) {
                const int r = wn * WN + nt * 8 + g;
                rb[nt][0] = *(const unsigned*)&Bc[r * BST + kk + t2];
                rb[nt][1] = *(const unsigned*)&Bc[r * BST + kk + t2 + 8];
            }
#pragma unroll
            for (int mt = 0; mt < MT; mt++) {
                const int r = wm * WM + mt * 16 + g;
                unsigned ra[4];
                ra[0] = *(const unsigned*)&Ac[r       * AST + kk + t2];
                ra[1] = *(const unsigned*)&Ac[(r + 8) * AST + kk + t2];
                ra[2] = *(const unsigned*)&Ac[r       * AST + kk + t2 + 8];
                ra[3] = *(const unsigned*)&Ac[(r + 8) * AST + kk + t2 + 8];
#pragma unroll
                for (int nt = 0; nt < NT; nt++)
                    mma16816(acc[mt][nt], ra, rb[nt]);
            }
        }
        __syncthreads();
    }

    // ---------------- epilogue ----------------
#pragma unroll
    for (int mt = 0; mt < MT; mt++) {
#pragma unroll
        for (int nt = 0; nt < NT; nt++) {
            const int row0 = m0 + wm * WM + mt * 16 + g;
            const int col  = n0 + wn * WN + nt * 8 + t2;
#pragma unroll
            for (int half = 0; half < 2; half++) {
                const int row = row0 + half * 8;
                float v0 = acc[mt][nt][half * 2 + 0];
                float v1 = acc[mt][nt][half * 2 + 1];
                if (bias)  { v0 += bias[col]; v1 += bias[col + 1]; }
                if (resid) { v0 += resid[(long)row * ldr + col];
                             v1 += resid[(long)row * ldr + col + 1]; }
                if (ACT == 1) {
                    v0 = 0.5f * v0 * (1.0f + erff(v0 * 0.70710678118654752f));
                    v1 = 0.5f * v1 * (1.0f + erff(v1 * 0.70710678118654752f));
                }
                if (OUTH) {
                    *(unsigned*)((__half*)Cv + (long)row * ldc + col) = packf2(v0, v1);
                } else {
                    float2 w; w.x = v0; w.y = v1;
                    *(float2*)((float*)Cv + (long)row * ldc + col) = w;
                }
            }
        }
    }
}

// ---------------- launcher ----------------
extern "C" void kernel_launch(void* const* d_in, const int* in_sizes, int n_in,
                              void* d_out, int out_size)
{
    const float* q     = (const float*)d_in[0];
    const float* kv    = (const float*)d_in[1];
    const float* n1g   = (const float*)d_in[2];
    const float* n1b   = (const float*)d_in[3];
    const float* qkv_w = (const float*)d_in[4];
    const float* sa_pw = (const float*)d_in[5];
    const float* sa_pb = (const float*)d_in[6];
    const float* n2qg  = (const float*)d_in[7];
    const float* n2qb  = (const float*)d_in[8];
    const float* n2kg  = (const float*)d_in[9];
    const float* n2kb  = (const float*)d_in[10];
    const float* caq_w = (const float*)d_in[11];
    const float* cakv_w= (const float*)d_in[12];
    const float* cap_w = (const float*)d_in[13];
    const float* cap_b = (const float*)d_in[14];
    const float* n3g   = (const float*)d_in[15];
    const float* n3b   = (const float*)d_in[16];
    const float* fc1w  = (const float*)d_in[17];
    const float* fc1b  = (const float*)d_in[18];
    const float* fc2w  = (const float*)d_in[19];
    const float* fc2b  = (const float*)d_in[20];
    float* out = (float*)d_out;

    __half *x, *xkv, *qkvb, *attn, *qh, *kvp, *hid;
    __half *wqkv, *wsa, *wcaq, *wcakv, *wcap, *wfc1, *wfc2;
    float *q1, *q2;
    cudaGetSymbolAddress((void**)&x,    g_x);
    cudaGetSymbolAddress((void**)&xkv,  g_xkv);
    cudaGetSymbolAddress((void**)&qkvb, g_qkv);
    cudaGetSymbolAddress((void**)&attn, g_attn);
    cudaGetSymbolAddress((void**)&qh,   g_qh);
    cudaGetSymbolAddress((void**)&kvp,  g_kvp);
    cudaGetSymbolAddress((void**)&q1,   g_q1);
    cudaGetSymbolAddress((void**)&q2,   g_q2);
    cudaGetSymbolAddress((void**)&hid,  g_hid);
    cudaGetSymbolAddress((void**)&wqkv, g_wqkv);
    cudaGetSymbolAddress((void**)&wsa,  g_wsa);
    cudaGetSymbolAddress((void**)&wcaq, g_wcaq);
    cudaGetSymbolAddress((void**)&wcakv,g_wcakv);
    cudaGetSymbolAddress((void**)&wcap, g_wcap);
    cudaGetSymbolAddress((void**)&wfc1, g_wfc1);
    cudaGetSymbolAddress((void**)&wfc2, g_wfc2);

    const int SM_MAIN = (128*40 + 128*40) * 2 * 2;   // 40960 B (2 stages)
    cudaFuncSetAttribute(mma_gemm<128,128,32,64,32,0,true>,
                         cudaFuncAttributeMaxDynamicSharedMemorySize, SM_MAIN);
    cudaFuncSetAttribute(mma_gemm<128,128,32,64,32,0,false>,
                         cudaFuncAttributeMaxDynamicSharedMemorySize, SM_MAIN);
    cudaFuncSetAttribute(mma_gemm<128,128,32,64,32,1,true>,
                         cudaFuncAttributeMaxDynamicSharedMemorySize, SM_MAIN);
    cudaFuncSetAttribute(flash_kernel,
                         cudaFuncAttributeMaxDynamicSharedMemorySize, FLASH_SMEM);

    const dim3 blk(256);
    const long QKV_B = (long)LQn * 3 * Dm;
    const long TOK_B = (long)LQn * Dm;
    const long KVP_B = (long)LKVn * 2 * Dm;

    // ---- weight conversion (merged) ----
    {
        CvtArgs a;
        a.s[0]=qkv_w;  a.d[0]=wqkv;  a.n[0]=3*Dm*Dm;
        a.s[1]=sa_pw;  a.d[1]=wsa;   a.n[1]=Dm*Dm;
        a.s[2]=caq_w;  a.d[2]=wcaq;  a.n[2]=Dm*Dm;
        a.s[3]=cakv_w; a.d[3]=wcakv; a.n[3]=2*Dm*Dm;
        a.s[4]=cap_w;  a.d[4]=wcap;  a.n[4]=Dm*Dm;
        a.s[5]=fc1w;   a.d[5]=wfc1;  a.n[5]=HIDn*Dm;
        a.s[6]=fc2w;   a.d[6]=wfc2;  a.n[6]=Dm*HIDn;
        cvt_all<<<dim3((HIDn*Dm + 255)/256, 7), 256>>>(a);
    }

    // ===== self-attention =====
    ln_kernel<<<NTOK, 256>>>(q, n1g, n1b, x);

    mma_gemm<128,128,32,64,32,0,true><<<dim3(3*Dm/128, NTOK/128), blk, SM_MAIN>>>(
        x, Dm, wqkv, Dm, qkvb, 3*Dm, Dm, nullptr, nullptr, 0);

    flash_kernel<<<dim3(LQn/128, Bq*Hn), blk, FLASH_SMEM>>>(
        qkvb,        3*Dm, QKV_B,
        qkvb + Dm,   3*Dm, QKV_B,
        qkvb + 2*Dm, 3*Dm, QKV_B,
        attn, Dm, TOK_B);

    mma_gemm<128,128,32,64,32,0,false><<<dim3(Dm/128, NTOK/128), blk, SM_MAIN>>>(
        attn, Dm, wsa, Dm, q1, Dm, Dm, sa_pb, q, Dm);

    // ===== cross-attention =====
    ln_kernel<<<NTOK, 256>>>(q1, n2qg, n2qb, x);
    ln_kernel<<<NTOK, 256>>>(kv, n2kg, n2kb, xkv);

    mma_gemm<128,128,32,64,32,0,true><<<dim3(Dm/128, NTOK/128), blk, SM_MAIN>>>(
        x, Dm, wcaq, Dm, qh, Dm, Dm, nullptr, nullptr, 0);

    mma_gemm<128,128,32,64,32,0,true><<<dim3(2*Dm/128, NTOK/128), blk, SM_MAIN>>>(
        xkv, Dm, wcakv, Dm, kvp, 2*Dm, Dm, nullptr, nullptr, 0);

    flash_kernel<<<dim3(LQn/128, Bq*Hn), blk, FLASH_SMEM>>>(
        qh,        Dm,   TOK_B,
        kvp,       2*Dm, KVP_B,
        kvp + Dm,  2*Dm, KVP_B,
        attn, Dm, TOK_B);

    mma_gemm<128,128,32,64,32,0,false><<<dim3(Dm/128, NTOK/128), blk, SM_MAIN>>>(
        attn, Dm, wcap, Dm, q2, Dm, Dm, cap_b, q1, Dm);

    // ===== MLP =====
    ln_kernel<<<NTOK, 256>>>(q2, n3g, n3b, x);

    mma_gemm<128,128,32,64,32,1,true><<<dim3(HIDn/128, NTOK/128), blk, SM_MAIN>>>(
        x, Dm, wfc1, Dm, hid, HIDn, Dm, fc1b, nullptr, 0);

    mma_gemm<128,128,32,64,32,0,false><<<dim3(Dm/128, NTOK/128), blk, SM_MAIN>>>(
        hid, HIDn, wfc2, HIDn, out, Dm, HIDn, fc2b, q2, Dm);
}

// round 12
// speedup vs baseline: 3.4791x; 3.4791x over previous
#include <cuda_runtime.h>
#include <cuda_fp16.h>
#include <math.h>

// ---------------- problem constants ----------------
#define Bq   16
#define LQn  512
#define LKVn 512
#define Dm   768
#define Hn   12
#define HDn  64
#define HIDn 3072
#define NTOK (Bq*LQn)          // 8192

// ---------------- scratch (device globals, plain fp16) ----------------
__device__ __align__(16) __half g_x   [NTOK*Dm];
__device__ __align__(16) __half g_xkv [NTOK*Dm];
__device__ __align__(16) __half g_qkv [NTOK*3*Dm];
__device__ __align__(16) __half g_attn[NTOK*Dm];
__device__ __align__(16) __half g_qh  [NTOK*Dm];
__device__ __align__(16) __half g_kvp [NTOK*2*Dm];
__device__ float  g_q1  [NTOK*Dm];
__device__ float  g_q2  [NTOK*Dm];
__device__ __align__(16) __half g_hid [NTOK*HIDn];
// converted weights
__device__ __align__(16) __half g_wqkv [3*Dm*Dm];
__device__ __align__(16) __half g_wsa  [Dm*Dm];
__device__ __align__(16) __half g_wcaq [Dm*Dm];
__device__ __align__(16) __half g_wcakv[2*Dm*Dm];
__device__ __align__(16) __half g_wcap [Dm*Dm];
__device__ __align__(16) __half g_wfc1 [HIDn*Dm];
__device__ __align__(16) __half g_wfc2 [Dm*HIDn];

// ---------------- helpers ----------------
__device__ __forceinline__ float warp_sum(float v){
#pragma unroll
    for (int o = 16; o > 0; o >>= 1) v += __shfl_xor_sync(0xffffffffu, v, o);
    return v;
}

__device__ __forceinline__ void mma16816(float* c, const unsigned* a, const unsigned* b){
    asm volatile(
        "mma.sync.aligned.m16n8k16.row.col.f32.f16.f16.f32 "
        "{%0,%1,%2,%3},{%4,%5,%6,%7},{%8,%9},{%0,%1,%2,%3};"
        : "+f"(c[0]), "+f"(c[1]), "+f"(c[2]), "+f"(c[3])
        : "r"(a[0]), "r"(a[1]), "r"(a[2]), "r"(a[3]), "r"(b[0]), "r"(b[1]));
}

__device__ __forceinline__ void cp16(void* smem_dst, const void* gsrc){
    unsigned s = (unsigned)__cvta_generic_to_shared(smem_dst);
    asm volatile("cp.async.cg.shared.global [%0], [%1], 16;\n" :: "r"(s), "l"(gsrc));
}
#define CP_COMMIT()  asm volatile("cp.async.commit_group;\n" ::: "memory")
#define CP_WAIT_1()  asm volatile("cp.async.wait_group 1;\n" ::: "memory")
#define CP_WAIT_0()  asm volatile("cp.async.wait_group 0;\n" ::: "memory")

// pack two fp32 into f16x2 register (low16 = p0)
__device__ __forceinline__ unsigned packf2(float p0, float p1){
    unsigned r;
    asm("cvt.rn.f16x2.f32 %0, %1, %2;" : "=r"(r) : "f"(p1), "f"(p0));
    return r;
}

// ---------------- merged weight conversion (blockIdx.y = segment) ----------------
struct CvtArgs {
    const float* s[7];
    __half*      d[7];
    int          n[7];
};
__global__ void cvt_all(CvtArgs a){
    const int seg = blockIdx.y;
    const int i = blockIdx.x * 256 + threadIdx.x;
    if (i < a.n[seg]) a.d[seg][i] = __float2half_rn(a.s[seg][i]);
}

// ---------------- LayerNorm -> fp16 ----------------
__global__ void ln_kernel(const float* __restrict__ x, const float* __restrict__ g,
                          const float* __restrict__ b, __half* __restrict__ y)
{
    __shared__ float sh[8];
    const long row = blockIdx.x;
    const float* xr = x + row * Dm;
    __half* yr = y + row * Dm;
    const int tid = threadIdx.x;
    const int w = tid >> 5, l = tid & 31;

    float v0 = xr[tid], v1 = xr[tid + 256], v2 = xr[tid + 512];

    float s = warp_sum(v0 + v1 + v2);
    if (l == 0) sh[w] = s;
    __syncthreads();
    if (w == 0) { float t = (l < 8) ? sh[l] : 0.f; t = warp_sum(t); if (l == 0) sh[0] = t; }
    __syncthreads();
    const float mean = sh[0] * (1.f / 768.f);
    __syncthreads();

    const float d0 = v0 - mean, d1 = v1 - mean, d2 = v2 - mean;
    float s2 = warp_sum(d0*d0 + d1*d1 + d2*d2);
    if (l == 0) sh[w] = s2;
    __syncthreads();
    if (w == 0) { float t = (l < 8) ? sh[l] : 0.f; t = warp_sum(t); if (l == 0) sh[0] = t; }
    __syncthreads();
    const float inv = rsqrtf(sh[0] * (1.f / 768.f) + 1e-5f);

    yr[tid]       = __float2half_rn(d0 * inv * g[tid]       + b[tid]);
    yr[tid + 256] = __float2half_rn(d1 * inv * g[tid + 256] + b[tid + 256]);
    yr[tid + 512] = __float2half_rn(d2 * inv * g[tid + 512] + b[tid + 512]);
}

// ---------------- fused flash attention (fp16 in/out, 128 Q-rows x 512 keys) ----------------
#define QS_ST 72
#define KS_ST 72
#define VS_ST 72
#define Q_TILE (128*QS_ST)   // halves
#define K_TILE (128*KS_ST)
#define V_TILE (128*VS_ST)
#define FLASH_SMEM ((Q_TILE + 2*K_TILE + 2*V_TILE) * 2)   // 92160 B

__global__ void __launch_bounds__(256, 1)
flash_kernel(const __half* __restrict__ Q, int ldq, long Qb,
             const __half* __restrict__ K, int ldk, long Kb,
             const __half* __restrict__ V, int ldv, long Vb,
             __half* __restrict__ O, int ldo, long Ob)
{
    extern __shared__ __half smh[];
    __half* Qs = smh;
    __half* Ks = smh + Q_TILE;
    __half* Vs = smh + Q_TILE + 2*K_TILE;

    const int tid  = threadIdx.x;
    const int wid  = tid >> 5, lane = tid & 31;
    const int g    = lane >> 2, t2 = (lane & 3) * 2;
    const int m0   = blockIdx.x * 128;
    const int wrow = wid * 16;

    {
        const int z = blockIdx.y;
        const int bb = z / Hn, hh = z - bb * Hn;
        Q += (long)bb * Qb + hh * 64;
        K += (long)bb * Kb + hh * 64;
        V += (long)bb * Vb + hh * 64;
        O += (long)bb * Ob + hh * 64;
    }

    auto loadQ = [&](){
#pragma unroll
        for (int idx = tid; idx < 1024; idx += 256) {
            const int r = idx >> 3, c = idx & 7;
            cp16(&Qs[r * QS_ST + c * 8], Q + (long)(m0 + r) * ldq + c * 8);
        }
    };
    auto loadK = [&](int kt, int s){
        __half* dst = Ks + s * K_TILE;
#pragma unroll
        for (int idx = tid; idx < 1024; idx += 256) {
            const int r = idx >> 3, c = idx & 7;
            cp16(&dst[r * KS_ST + c * 8], K + (long)(kt * 128 + r) * ldk + c * 8);
        }
    };
    auto loadV = [&](int kt, int s){
        __half* dst = Vs + s * V_TILE;
#pragma unroll
        for (int idx = tid; idx < 1024; idx += 256) {
            const int r = idx >> 3, c = idx & 7;
            cp16(&dst[r * VS_ST + c * 8], V + (long)(kt * 128 + r) * ldv + c * 8);
        }
    };

    float o[8][4];
#pragma unroll
    for (int i = 0; i < 8; i++)
#pragma unroll
        for (int j = 0; j < 4; j++) o[i][j] = 0.f;
    float m_a = -1e30f, m_b = -1e30f, l_a = 0.f, l_b = 0.f;

    loadQ(); loadK(0, 0); loadV(0, 0); CP_COMMIT();
    loadK(1, 1); loadV(1, 1); CP_COMMIT();

    for (int it = 0; it < 4; it++) {
        if (it >= 1) {
            __syncthreads();
            if (it + 1 < 4) { loadK(it + 1, (it + 1) & 1); loadV(it + 1, (it + 1) & 1); CP_COMMIT(); }
        }
        if (it + 1 < 4) CP_WAIT_1(); else CP_WAIT_0();
        __syncthreads();

        const __half* Kc = Ks + (it & 1) * K_TILE;
        const __half* Vc = Vs + (it & 1) * V_TILE;

        // ---- S = Q K^T ----
        float s[16][4];
#pragma unroll
        for (int nt = 0; nt < 16; nt++)
#pragma unroll
            for (int c = 0; c < 4; c++) s[nt][c] = 0.f;

#pragma unroll
        for (int kk = 0; kk < 64; kk += 16) {
            const int r = wrow + g;
            unsigned ra[4];
            ra[0] = *(const unsigned*)&Qs[r       * QS_ST + kk + t2];
            ra[1] = *(const unsigned*)&Qs[(r + 8) * QS_ST + kk + t2];
            ra[2] = *(const unsigned*)&Qs[r       * QS_ST + kk + t2 + 8];
            ra[3] = *(const unsigned*)&Qs[(r + 8) * QS_ST + kk + t2 + 8];
#pragma unroll
            for (int nt = 0; nt < 16; nt++) {
                const int kr = nt * 8 + g;
                unsigned rb[2];
                rb[0] = *(const unsigned*)&Kc[kr * KS_ST + kk + t2];
                rb[1] = *(const unsigned*)&Kc[kr * KS_ST + kk + t2 + 8];
                mma16816(s[nt], ra, rb);
            }
        }

        // ---- online softmax (scale 1/8 folded) ----
        float mx_a = -1e30f, mx_b = -1e30f;
#pragma unroll
        for (int nt = 0; nt < 16; nt++) {
#pragma unroll
            for (int c = 0; c < 4; c++) s[nt][c] *= 0.125f;
            mx_a = fmaxf(mx_a, fmaxf(s[nt][0], s[nt][1]));
            mx_b = fmaxf(mx_b, fmaxf(s[nt][2], s[nt][3]));
        }
        mx_a = fmaxf(mx_a, __shfl_xor_sync(0xffffffffu, mx_a, 1));
        mx_a = fmaxf(mx_a, __shfl_xor_sync(0xffffffffu, mx_a, 2));
        mx_b = fmaxf(mx_b, __shfl_xor_sync(0xffffffffu, mx_b, 1));
        mx_b = fmaxf(mx_b, __shfl_xor_sync(0xffffffffu, mx_b, 2));

        const float nm_a = fmaxf(m_a, mx_a);
        const float nm_b = fmaxf(m_b, mx_b);
        const float sc_a = __expf(m_a - nm_a);
        const float sc_b = __expf(m_b - nm_b);
        m_a = nm_a; m_b = nm_b;
        l_a *= sc_a; l_b *= sc_b;
#pragma unroll
        for (int nt = 0; nt < 8; nt++) {
            o[nt][0] *= sc_a; o[nt][1] *= sc_a;
            o[nt][2] *= sc_b; o[nt][3] *= sc_b;
        }
        float sum_a = 0.f, sum_b = 0.f;
#pragma unroll
        for (int nt = 0; nt < 16; nt++) {
            s[nt][0] = __expf(s[nt][0] - nm_a);
            s[nt][1] = __expf(s[nt][1] - nm_a);
            s[nt][2] = __expf(s[nt][2] - nm_b);
            s[nt][3] = __expf(s[nt][3] - nm_b);
            sum_a += s[nt][0] + s[nt][1];
            sum_b += s[nt][2] + s[nt][3];
        }
        l_a += sum_a; l_b += sum_b;

        // ---- O += P V ----
        const unsigned short* Vu = (const unsigned short*)Vc;
#pragma unroll
        for (int ks = 0; ks < 8; ks++) {
            unsigned ra[4];
            ra[0] = packf2(s[2*ks  ][0], s[2*ks  ][1]);
            ra[1] = packf2(s[2*ks  ][2], s[2*ks  ][3]);
            ra[2] = packf2(s[2*ks+1][0], s[2*ks+1][1]);
            ra[3] = packf2(s[2*ks+1][2], s[2*ks+1][3]);
            const int r0 = ks * 16 + t2;
#pragma unroll
            for (int nt = 0; nt < 8; nt++) {
                const int n = nt * 8 + g;
                unsigned b0 = (unsigned)Vu[(r0    ) * VS_ST + n]
                            | ((unsigned)Vu[(r0 + 1) * VS_ST + n] << 16);
                unsigned b1 = (unsigned)Vu[(r0 + 8) * VS_ST + n]
                            | ((unsigned)Vu[(r0 + 9) * VS_ST + n] << 16);
                unsigned rb[2] = {b0, b1};
                mma16816(o[nt], ra, rb);
            }
        }
    }

    l_a += __shfl_xor_sync(0xffffffffu, l_a, 1);
    l_a += __shfl_xor_sync(0xffffffffu, l_a, 2);
    l_b += __shfl_xor_sync(0xffffffffu, l_b, 1);
    l_b += __shfl_xor_sync(0xffffffffu, l_b, 2);
    const float inv_a = 1.f / l_a;
    const float inv_b = 1.f / l_b;

    const int row_a = m0 + wrow + g;
    const int row_b = row_a + 8;
#pragma unroll
    for (int nt = 0; nt < 8; nt++) {
        const int col = nt * 8 + t2;
        *(unsigned*)&O[(long)row_a * ldo + col] = packf2(o[nt][0] * inv_a, o[nt][1] * inv_a);
        *(unsigned*)&O[(long)row_b * ldo + col] = packf2(o[nt][2] * inv_b, o[nt][3] * inv_b);
    }
}

// ---------------- fp16 tensor-core GEMM, 2-stage cp.async, 3 CTAs/SM, 128x64 tile ----------------
// C[m,n] = sum_k A[m,k]*B[n,k]. ACT==1: exact GELU. OUTH: fp16 out else fp32 (+bias/resid).
template<int BM, int BN, int BK, int WM, int WN, int ACT, bool OUTH>
__global__ void __launch_bounds__(256, 3)
mma_gemm(const __half* __restrict__ A, int lda,
         const __half* __restrict__ B, int ldb,
         void* __restrict__ Cv, int ldc,
         int K,
         const float* __restrict__ bias,
         const float* __restrict__ resid, int ldr)
{
    constexpr int AST   = BK + 8;                      // 40 halves (80 B)
    constexpr int BST   = BK + 8;
    constexpr int A_TILE = BM * AST;                   // halves
    constexpr int B_TILE = BN * BST;
    constexpr int STAGE  = A_TILE + B_TILE;
    constexpr int NWN = BN / WN;
    constexpr int MT  = WM / 16;
    constexpr int NT  = WN / 8;

    extern __shared__ __half smh[];

    const int tid = threadIdx.x;
    const int wid = tid >> 5, lane = tid & 31;
    const int wm = wid / NWN, wn = wid % NWN;
    const int g  = lane >> 2, t2 = (lane & 3) * 2;

    const int m0 = blockIdx.y * BM, n0 = blockIdx.x * BN;

    float acc[MT][NT][4];
#pragma unroll
    for (int i = 0; i < MT; i++)
#pragma unroll
        for (int j = 0; j < NT; j++)
#pragma unroll
            for (int c = 0; c < 4; c++) acc[i][j][c] = 0.f;

    auto load_tiles = [&](int k0, int s){
        __half* Ad = smh + s * STAGE;
        __half* Bd = Ad + A_TILE;
        constexpr int ACH = BM * BK / 8;               // 16B chunks
#pragma unroll
        for (int idx = tid; idx < ACH; idx += 256) {
            const int r = idx / (BK / 8), c = idx % (BK / 8);
            cp16(&Ad[r * AST + c * 8], A + (long)(m0 + r) * lda + k0 + c * 8);
        }
        constexpr int BCH = BN * BK / 8;
#pragma unroll
        for (int idx = tid; idx < BCH; idx += 256) {
            const int r = idx / (BK / 8), c = idx % (BK / 8);
            cp16(&Bd[r * BST + c * 8], B + (long)(n0 + r) * ldb + k0 + c * 8);
        }
    };

    const int iters = K / BK;
    load_tiles(0, 0);
    CP_COMMIT();

    for (int it = 0; it < iters; it++) {
        if (it + 1 < iters) {
            load_tiles((it + 1) * BK, (it + 1) & 1);
            CP_COMMIT();
            CP_WAIT_1();
        } else {
            CP_WAIT_0();
        }
        __syncthreads();

        const __half* Ac = smh + (it & 1) * STAGE;
        const __half* Bc = Ac + A_TILE;

#pragma unroll
        for (int kk = 0; kk < BK; kk += 16) {
            unsigned rb[NT][2];
#pragma unroll
            for (int nt = 0; nt < NT; nt++) {
                const int r = wn * WN + nt * 8 + g;
                rb[nt][0] = *(const unsigned*)&Bc[r * BST + kk + t2];
                rb[nt][1] = *(const unsigned*)&Bc[r * BST + kk + t2 + 8];
            }
#pragma unroll
            for (int mt = 0; mt < MT; mt++) {
                const int r = wm * WM + mt * 16 + g;
                unsigned ra[4];
                ra[0] = *(const unsigned*)&Ac[r       * AST + kk + t2];
                ra[1] = *(const unsigned*)&Ac[(r + 8) * AST + kk + t2];
                ra[2] = *(const unsigned*)&Ac[r       * AST + kk + t2 + 8];
                ra[3] = *(const unsigned*)&Ac[(r + 8) * AST + kk + t2 + 8];
#pragma unroll
                for (int nt = 0; nt < NT; nt++)
                    mma16816(acc[mt][nt], ra, rb[nt]);
            }
        }
        __syncthreads();
    }

    // ---------------- epilogue ----------------
#pragma unroll
    for (int mt = 0; mt < MT; mt++) {
#pragma unroll
        for (int nt = 0; nt < NT; nt++) {
            const int row0 = m0 + wm * WM + mt * 16 + g;
            const int col  = n0 + wn * WN + nt * 8 + t2;
#pragma unroll
            for (int half = 0; half < 2; half++) {
                const int row = row0 + half * 8;
                float v0 = acc[mt][nt][half * 2 + 0];
                float v1 = acc[mt][nt][half * 2 + 1];
                if (bias)  { v0 += bias[col]; v1 += bias[col + 1]; }
                if (resid) { v0 += resid[(long)row * ldr + col];
                             v1 += resid[(long)row * ldr + col + 1]; }
                if (ACT == 1) {
                    v0 = 0.5f * v0 * (1.0f + erff(v0 * 0.70710678118654752f));
                    v1 = 0.5f * v1 * (1.0f + erff(v1 * 0.70710678118654752f));
                }
                if (OUTH) {
                    *(unsigned*)((__half*)Cv + (long)row * ldc + col) = packf2(v0, v1);
                } else {
                    float2 w; w.x = v0; w.y = v1;
                    *(float2*)((float*)Cv + (long)row * ldc + col) = w;
                }
            }
        }
    }
}

// ---------------- launcher ----------------
extern "C" void kernel_launch(void* const* d_in, const int* in_sizes, int n_in,
                              void* d_out, int out_size)
{
    const float* q     = (const float*)d_in[0];
    const float* kv    = (const float*)d_in[1];
    const float* n1g   = (const float*)d_in[2];
    const float* n1b   = (const float*)d_in[3];
    const float* qkv_w = (const float*)d_in[4];
    const float* sa_pw = (const float*)d_in[5];
    const float* sa_pb = (const float*)d_in[6];
    const float* n2qg  = (const float*)d_in[7];
    const float* n2qb  = (const float*)d_in[8];
    const float* n2kg  = (const float*)d_in[9];
    const float* n2kb  = (const float*)d_in[10];
    const float* caq_w = (const float*)d_in[11];
    const float* cakv_w= (const float*)d_in[12];
    const float* cap_w = (const float*)d_in[13];
    const float* cap_b = (const float*)d_in[14];
    const float* n3g   = (const float*)d_in[15];
    const float* n3b   = (const float*)d_in[16];
    const float* fc1w  = (const float*)d_in[17];
    const float* fc1b  = (const float*)d_in[18];
    const float* fc2w  = (const float*)d_in[19];
    const float* fc2b  = (const float*)d_in[20];
    float* out = (float*)d_out;

    __half *x, *xkv, *qkvb, *attn, *qh, *kvp, *hid;
    __half *wqkv, *wsa, *wcaq, *wcakv, *wcap, *wfc1, *wfc2;
    float *q1, *q2;
    cudaGetSymbolAddress((void**)&x,    g_x);
    cudaGetSymbolAddress((void**)&xkv,  g_xkv);
    cudaGetSymbolAddress((void**)&qkvb, g_qkv);
    cudaGetSymbolAddress((void**)&attn, g_attn);
    cudaGetSymbolAddress((void**)&qh,   g_qh);
    cudaGetSymbolAddress((void**)&kvp,  g_kvp);
    cudaGetSymbolAddress((void**)&q1,   g_q1);
    cudaGetSymbolAddress((void**)&q2,   g_q2);
    cudaGetSymbolAddress((void**)&hid,  g_hid);
    cudaGetSymbolAddress((void**)&wqkv, g_wqkv);
    cudaGetSymbolAddress((void**)&wsa,  g_wsa);
    cudaGetSymbolAddress((void**)&wcaq, g_wcaq);
    cudaGetSymbolAddress((void**)&wcakv,g_wcakv);
    cudaGetSymbolAddress((void**)&wcap, g_wcap);
    cudaGetSymbolAddress((void**)&wfc1, g_wfc1);
    cudaGetSymbolAddress((void**)&wfc2, g_wfc2);

    const int SM_MAIN = (128*40 + 64*40) * 2 * 2;   // 30720 B (2 stages, BN=64)
    cudaFuncSetAttribute(mma_gemm<128,64,32,32,32,0,true>,
                         cudaFuncAttributeMaxDynamicSharedMemorySize, SM_MAIN);
    cudaFuncSetAttribute(mma_gemm<128,64,32,32,32,0,false>,
                         cudaFuncAttributeMaxDynamicSharedMemorySize, SM_MAIN);
    cudaFuncSetAttribute(mma_gemm<128,64,32,32,32,1,true>,
                         cudaFuncAttributeMaxDynamicSharedMemorySize, SM_MAIN);
    cudaFuncSetAttribute(flash_kernel,
                         cudaFuncAttributeMaxDynamicSharedMemorySize, FLASH_SMEM);

    const dim3 blk(256);
    const long QKV_B = (long)LQn * 3 * Dm;
    const long TOK_B = (long)LQn * Dm;
    const long KVP_B = (long)LKVn * 2 * Dm;

    // ---- weight conversion (merged) ----
    {
        CvtArgs a;
        a.s[0]=qkv_w;  a.d[0]=wqkv;  a.n[0]=3*Dm*Dm;
        a.s[1]=sa_pw;  a.d[1]=wsa;   a.n[1]=Dm*Dm;
        a.s[2]=caq_w;  a.d[2]=wcaq;  a.n[2]=Dm*Dm;
        a.s[3]=cakv_w; a.d[3]=wcakv; a.n[3]=2*Dm*Dm;
        a.s[4]=cap_w;  a.d[4]=wcap;  a.n[4]=Dm*Dm;
        a.s[5]=fc1w;   a.d[5]=wfc1;  a.n[5]=HIDn*Dm;
        a.s[6]=fc2w;   a.d[6]=wfc2;  a.n[6]=Dm*HIDn;
        cvt_all<<<dim3((HIDn*Dm + 255)/256, 7), 256>>>(a);
    }

    // ===== self-attention =====
    ln_kernel<<<NTOK, 256>>>(q, n1g, n1b, x);

    mma_gemm<128,64,32,32,32,0,true><<<dim3(3*Dm/64, NTOK/128), blk, SM_MAIN>>>(
        x, Dm, wqkv, Dm, qkvb, 3*Dm, Dm, nullptr, nullptr, 0);

    flash_kernel<<<dim3(LQn/128, Bq*Hn), blk, FLASH_SMEM>>>(
        qkvb,        3*Dm, QKV_B,
        qkvb + Dm,   3*Dm, QKV_B,
        qkvb + 2*Dm, 3*Dm, QKV_B,
        attn, Dm, TOK_B);

    mma_gemm<128,64,32,32,32,0,false><<<dim3(Dm/64, NTOK/128), blk, SM_MAIN>>>(
        attn, Dm, wsa, Dm, q1, Dm, Dm, sa_pb, q, Dm);

    // ===== cross-attention =====
    ln_kernel<<<NTOK, 256>>>(q1, n2qg, n2qb, x);
    ln_kernel<<<NTOK, 256>>>(kv, n2kg, n2kb, xkv);

    mma_gemm<128,64,32,32,32,0,true><<<dim3(Dm/64, NTOK/128), blk, SM_MAIN>>>(
        x, Dm, wcaq, Dm, qh, Dm, Dm, nullptr, nullptr, 0);

    mma_gemm<128,64,32,32,32,0,true><<<dim3(2*Dm/64, NTOK/128), blk, SM_MAIN>>>(
        xkv, Dm, wcakv, Dm, kvp, 2*Dm, Dm, nullptr, nullptr, 0);

    flash_kernel<<<dim3(LQn/128, Bq*Hn), blk, FLASH_SMEM>>>(
        qh,        Dm,   TOK_B,
        kvp,       2*Dm, KVP_B,
        kvp + Dm,  2*Dm, KVP_B,
        attn, Dm, TOK_B);

    mma_gemm<128,64,32,32,32,0,false><<<dim3(Dm/64, NTOK/128), blk, SM_MAIN>>>(
        attn, Dm, wcap, Dm, q2, Dm, Dm, cap_b, q1, Dm);

    // ===== MLP =====
    ln_kernel<<<NTOK, 256>>>(q2, n3g, n3b, x);

    mma_gemm<128,64,32,32,32,1,true><<<dim3(HIDn/64, NTOK/128), blk, SM_MAIN>>>(
        x, Dm, wfc1, Dm, hid, HIDn, Dm, fc1b, nullptr, 0);

    mma_gemm<128,64,32,32,32,0,false><<<dim3(Dm/64, NTOK/128), blk, SM_MAIN>>>(
        hid, HIDn, wfc2, HIDn, out, Dm, HIDn, fc2b, q2, Dm);
}

// round 13
// speedup vs baseline: 3.9984x; 1.1493x over previous
#include <cuda_runtime.h>
#include <cuda_fp16.h>
#include <math.h>

// ---------------- problem constants ----------------
#define Bq   16
#define LQn  512
#define LKVn 512
#define Dm   768
#define Hn   12
#define HDn  64
#define HIDn 3072
#define NTOK (Bq*LQn)          // 8192

// ---------------- scratch (device globals, plain fp16) ----------------
__device__ __align__(16) __half g_x   [NTOK*Dm];
__device__ __align__(16) __half g_xkv [NTOK*Dm];
__device__ __align__(16) __half g_qkv [NTOK*3*Dm];
__device__ __align__(16) __half g_attn[NTOK*Dm];
__device__ __align__(16) __half g_qh  [NTOK*Dm];
__device__ __align__(16) __half g_kvp [NTOK*2*Dm];
__device__ float  g_q1  [NTOK*Dm];
__device__ float  g_q2  [NTOK*Dm];
__device__ __align__(16) __half g_hid [NTOK*HIDn];
// converted weights
__device__ __align__(16) __half g_wqkv [3*Dm*Dm];
__device__ __align__(16) __half g_wsa  [Dm*Dm];
__device__ __align__(16) __half g_wcaq [Dm*Dm];
__device__ __align__(16) __half g_wcakv[2*Dm*Dm];
__device__ __align__(16) __half g_wcap [Dm*Dm];
__device__ __align__(16) __half g_wfc1 [HIDn*Dm];
__device__ __align__(16) __half g_wfc2 [Dm*HIDn];

// ---------------- helpers ----------------
__device__ __forceinline__ float warp_sum(float v){
#pragma unroll
    for (int o = 16; o > 0; o >>= 1) v += __shfl_xor_sync(0xffffffffu, v, o);
    return v;
}

__device__ __forceinline__ void mma16816(float* c, const unsigned* a, const unsigned* b){
    asm volatile(
        "mma.sync.aligned.m16n8k16.row.col.f32.f16.f16.f32 "
        "{%0,%1,%2,%3},{%4,%5,%6,%7},{%8,%9},{%0,%1,%2,%3};"
        : "+f"(c[0]), "+f"(c[1]), "+f"(c[2]), "+f"(c[3])
        : "r"(a[0]), "r"(a[1]), "r"(a[2]), "r"(a[3]), "r"(b[0]), "r"(b[1]));
}

__device__ __forceinline__ void cp16(void* smem_dst, const void* gsrc){
    unsigned s = (unsigned)__cvta_generic_to_shared(smem_dst);
    asm volatile("cp.async.cg.shared.global [%0], [%1], 16;\n" :: "r"(s), "l"(gsrc));
}
#define CP_COMMIT()  asm volatile("cp.async.commit_group;\n" ::: "memory")
#define CP_WAIT_1()  asm volatile("cp.async.wait_group 1;\n" ::: "memory")
#define CP_WAIT_0()  asm volatile("cp.async.wait_group 0;\n" ::: "memory")

// pack two fp32 into f16x2 register (low16 = p0)
__device__ __forceinline__ unsigned packf2(float p0, float p1){
    unsigned r;
    asm("cvt.rn.f16x2.f32 %0, %1, %2;" : "=r"(r) : "f"(p1), "f"(p0));
    return r;
}

// ---------------- merged weight conversion (blockIdx.y = segment) ----------------
struct CvtArgs {
    const float* s[7];
    __half*      d[7];
    int          n[7];
};
__global__ void cvt_all(CvtArgs a){
    const int seg = blockIdx.y;
    const int i = blockIdx.x * 256 + threadIdx.x;
    if (i < a.n[seg]) a.d[seg][i] = __float2half_rn(a.s[seg][i]);
}

// ---------------- LayerNorm, warp-per-row (no barriers) -> fp16 ----------------
__global__ void ln_kernel(const float* __restrict__ x, const float* __restrict__ g,
                          const float* __restrict__ b, __half* __restrict__ y)
{
    const int wid = threadIdx.x >> 5, lane = threadIdx.x & 31;
    const long row = (long)blockIdx.x * 8 + wid;
    const float* xr = x + row * Dm;

    float4 v[6];
    float s = 0.f;
#pragma unroll
    for (int i = 0; i < 6; i++) {
        v[i] = *(const float4*)(xr + i * 128 + lane * 4);
        s += v[i].x + v[i].y + v[i].z + v[i].w;
    }
    s = warp_sum(s);
    const float mean = s * (1.f / 768.f);

    float s2 = 0.f;
#pragma unroll
    for (int i = 0; i < 6; i++) {
        v[i].x -= mean; v[i].y -= mean; v[i].z -= mean; v[i].w -= mean;
        s2 += v[i].x*v[i].x + v[i].y*v[i].y + v[i].z*v[i].z + v[i].w*v[i].w;
    }
    s2 = warp_sum(s2);
    const float inv = rsqrtf(s2 * (1.f / 768.f) + 1e-5f);

    __half* yr = y + row * Dm;
#pragma unroll
    for (int i = 0; i < 6; i++) {
        const int c = i * 128 + lane * 4;
        float4 gg = *(const float4*)(g + c);
        float4 bb = *(const float4*)(b + c);
        uint2 w;
        w.x = packf2(v[i].x * inv * gg.x + bb.x, v[i].y * inv * gg.y + bb.y);
        w.y = packf2(v[i].z * inv * gg.z + bb.z, v[i].w * inv * gg.w + bb.w);
        *(uint2*)(yr + c) = w;
    }
}

// ---------------- fused flash attention (fp16 in/out, 128 Q-rows x 512 keys) ----------------
#define QS_ST 72
#define KS_ST 72
#define VS_ST 72
#define Q_TILE (128*QS_ST)   // halves
#define K_TILE (128*KS_ST)
#define V_TILE (128*VS_ST)
#define FLASH_SMEM ((Q_TILE + 2*K_TILE + 2*V_TILE) * 2)   // 92160 B

__global__ void __launch_bounds__(256, 1)
flash_kernel(const __half* __restrict__ Q, int ldq, long Qb,
             const __half* __restrict__ K, int ldk, long Kb,
             const __half* __restrict__ V, int ldv, long Vb,
             __half* __restrict__ O, int ldo, long Ob)
{
    extern __shared__ __half smh[];
    __half* Qs = smh;
    __half* Ks = smh + Q_TILE;
    __half* Vs = smh + Q_TILE + 2*K_TILE;

    const int tid  = threadIdx.x;
    const int wid  = tid >> 5, lane = tid & 31;
    const int g    = lane >> 2, t2 = (lane & 3) * 2;
    const int m0   = blockIdx.x * 128;
    const int wrow = wid * 16;

    {
        const int z = blockIdx.y;
        const int bb = z / Hn, hh = z - bb * Hn;
        Q += (long)bb * Qb + hh * 64;
        K += (long)bb * Kb + hh * 64;
        V += (long)bb * Vb + hh * 64;
        O += (long)bb * Ob + hh * 64;
    }

    auto loadQ = [&](){
#pragma unroll
        for (int idx = tid; idx < 1024; idx += 256) {
            const int r = idx >> 3, c = idx & 7;
            cp16(&Qs[r * QS_ST + c * 8], Q + (long)(m0 + r) * ldq + c * 8);
        }
    };
    auto loadK = [&](int kt, int s){
        __half* dst = Ks + s * K_TILE;
#pragma unroll
        for (int idx = tid; idx < 1024; idx += 256) {
            const int r = idx >> 3, c = idx & 7;
            cp16(&dst[r * KS_ST + c * 8], K + (long)(kt * 128 + r) * ldk + c * 8);
        }
    };
    auto loadV = [&](int kt, int s){
        __half* dst = Vs + s * V_TILE;
#pragma unroll
        for (int idx = tid; idx < 1024; idx += 256) {
            const int r = idx >> 3, c = idx & 7;
            cp16(&dst[r * VS_ST + c * 8], V + (long)(kt * 128 + r) * ldv + c * 8);
        }
    };

    float o[8][4];
#pragma unroll
    for (int i = 0; i < 8; i++)
#pragma unroll
        for (int j = 0; j < 4; j++) o[i][j] = 0.f;
    float m_a = -1e30f, m_b = -1e30f, l_a = 0.f, l_b = 0.f;

    loadQ(); loadK(0, 0); loadV(0, 0); CP_COMMIT();
    loadK(1, 1); loadV(1, 1); CP_COMMIT();

    for (int it = 0; it < 4; it++) {
        if (it >= 1) {
            __syncthreads();
            if (it + 1 < 4) { loadK(it + 1, (it + 1) & 1); loadV(it + 1, (it + 1) & 1); CP_COMMIT(); }
        }
        if (it + 1 < 4) CP_WAIT_1(); else CP_WAIT_0();
        __syncthreads();

        const __half* Kc = Ks + (it & 1) * K_TILE;
        const __half* Vc = Vs + (it & 1) * V_TILE;

        // ---- S = Q K^T ----
        float s[16][4];
#pragma unroll
        for (int nt = 0; nt < 16; nt++)
#pragma unroll
            for (int c = 0; c < 4; c++) s[nt][c] = 0.f;

#pragma unroll
        for (int kk = 0; kk < 64; kk += 16) {
            const int r = wrow + g;
            unsigned ra[4];
            ra[0] = *(const unsigned*)&Qs[r       * QS_ST + kk + t2];
            ra[1] = *(const unsigned*)&Qs[(r + 8) * QS_ST + kk + t2];
            ra[2] = *(const unsigned*)&Qs[r       * QS_ST + kk + t2 + 8];
            ra[3] = *(const unsigned*)&Qs[(r + 8) * QS_ST + kk + t2 + 8];
#pragma unroll
            for (int nt = 0; nt < 16; nt++) {
                const int kr = nt * 8 + g;
                unsigned rb[2];
                rb[0] = *(const unsigned*)&Kc[kr * KS_ST + kk + t2];
                rb[1] = *(const unsigned*)&Kc[kr * KS_ST + kk + t2 + 8];
                mma16816(s[nt], ra, rb);
            }
        }

        // ---- online softmax (scale 1/8 folded) ----
        float mx_a = -1e30f, mx_b = -1e30f;
#pragma unroll
        for (int nt = 0; nt < 16; nt++) {
#pragma unroll
            for (int c = 0; c < 4; c++) s[nt][c] *= 0.125f;
            mx_a = fmaxf(mx_a, fmaxf(s[nt][0], s[nt][1]));
            mx_b = fmaxf(mx_b, fmaxf(s[nt][2], s[nt][3]));
        }
        mx_a = fmaxf(mx_a, __shfl_xor_sync(0xffffffffu, mx_a, 1));
        mx_a = fmaxf(mx_a, __shfl_xor_sync(0xffffffffu, mx_a, 2));
        mx_b = fmaxf(mx_b, __shfl_xor_sync(0xffffffffu, mx_b, 1));
        mx_b = fmaxf(mx_b, __shfl_xor_sync(0xffffffffu, mx_b, 2));

        const float nm_a = fmaxf(m_a, mx_a);
        const float nm_b = fmaxf(m_b, mx_b);
        const float sc_a = __expf(m_a - nm_a);
        const float sc_b = __expf(m_b - nm_b);
        m_a = nm_a; m_b = nm_b;
        l_a *= sc_a; l_b *= sc_b;
#pragma unroll
        for (int nt = 0; nt < 8; nt++) {
            o[nt][0] *= sc_a; o[nt][1] *= sc_a;
            o[nt][2] *= sc_b; o[nt][3] *= sc_b;
        }
        float sum_a = 0.f, sum_b = 0.f;
#pragma unroll
        for (int nt = 0; nt < 16; nt++) {
            s[nt][0] = __expf(s[nt][0] - nm_a);
            s[nt][1] = __expf(s[nt][1] - nm_a);
            s[nt][2] = __expf(s[nt][2] - nm_b);
            s[nt][3] = __expf(s[nt][3] - nm_b);
            sum_a += s[nt][0] + s[nt][1];
            sum_b += s[nt][2] + s[nt][3];
        }
        l_a += sum_a; l_b += sum_b;

        // ---- O += P V ----
        const unsigned short* Vu = (const unsigned short*)Vc;
#pragma unroll
        for (int ks = 0; ks < 8; ks++) {
            unsigned ra[4];
            ra[0] = packf2(s[2*ks  ][0], s[2*ks  ][1]);
            ra[1] = packf2(s[2*ks  ][2], s[2*ks  ][3]);
            ra[2] = packf2(s[2*ks+1][0], s[2*ks+1][1]);
            ra[3] = packf2(s[2*ks+1][2], s[2*ks+1][3]);
            const int r0 = ks * 16 + t2;
#pragma unroll
            for (int nt = 0; nt < 8; nt++) {
                const int n = nt * 8 + g;
                unsigned b0 = (unsigned)Vu[(r0    ) * VS_ST + n]
                            | ((unsigned)Vu[(r0 + 1) * VS_ST + n] << 16);
                unsigned b1 = (unsigned)Vu[(r0 + 8) * VS_ST + n]
                            | ((unsigned)Vu[(r0 + 9) * VS_ST + n] << 16);
                unsigned rb[2] = {b0, b1};
                mma16816(o[nt], ra, rb);
            }
        }
    }

    l_a += __shfl_xor_sync(0xffffffffu, l_a, 1);
    l_a += __shfl_xor_sync(0xffffffffu, l_a, 2);
    l_b += __shfl_xor_sync(0xffffffffu, l_b, 1);
    l_b += __shfl_xor_sync(0xffffffffu, l_b, 2);
    const float inv_a = 1.f / l_a;
    const float inv_b = 1.f / l_b;

    const int row_a = m0 + wrow + g;
    const int row_b = row_a + 8;
#pragma unroll
    for (int nt = 0; nt < 8; nt++) {
        const int col = nt * 8 + t2;
        *(unsigned*)&O[(long)row_a * ldo + col] = packf2(o[nt][0] * inv_a, o[nt][1] * inv_a);
        *(unsigned*)&O[(long)row_b * ldo + col] = packf2(o[nt][2] * inv_b, o[nt][3] * inv_b);
    }
}

// ---------------- GEMM core (shared by single and dual variants) ----------------
#define AST  40
#define BST  40
#define A_TILE_H (128*AST)
#define B_TILE_H (128*BST)
#define STAGE_H  (A_TILE_H + B_TILE_H)
#define SM_MAIN  (STAGE_H * 2 * 2)     // 40960 B

template<int ACT, bool OUTH>
__device__ __forceinline__ void gemm_body(
    const __half* __restrict__ A, int lda,
    const __half* __restrict__ B, int ldb,
    void* __restrict__ Cv, int ldc,
    int K, int m0, int n0,
    const float* __restrict__ bias,
    const float* __restrict__ resid, int ldr,
    __half* smh)
{
    const int tid = threadIdx.x;
    const int wid = tid >> 5, lane = tid & 31;
    const int wm = wid >> 2, wn = wid & 3;            // 2x4 warp grid, 64x32 tiles
    const int g  = lane >> 2, t2 = (lane & 3) * 2;

    float acc[4][4][4];
#pragma unroll
    for (int i = 0; i < 4; i++)
#pragma unroll
        for (int j = 0; j < 4; j++)
#pragma unroll
            for (int c = 0; c < 4; c++) acc[i][j][c] = 0.f;

    auto load_tiles = [&](int k0, int s){
        __half* Ad = smh + s * STAGE_H;
        __half* Bd = Ad + A_TILE_H;
#pragma unroll
        for (int idx = tid; idx < 512; idx += 256) {
            const int r = idx >> 2, c = idx & 3;
            cp16(&Ad[r * AST + c * 8], A + (long)(m0 + r) * lda + k0 + c * 8);
        }
#pragma unroll
        for (int idx = tid; idx < 512; idx += 256) {
            const int r = idx >> 2, c = idx & 3;
            cp16(&Bd[r * BST + c * 8], B + (long)(n0 + r) * ldb + k0 + c * 8);
        }
    };

    const int iters = K / 32;
    load_tiles(0, 0);
    CP_COMMIT();

    for (int it = 0; it < iters; it++) {
        if (it + 1 < iters) {
            load_tiles((it + 1) * 32, (it + 1) & 1);
            CP_COMMIT();
            CP_WAIT_1();
        } else {
            CP_WAIT_0();
        }
        __syncthreads();

        const __half* Ac = smh + (it & 1) * STAGE_H;
        const __half* Bc = Ac + A_TILE_H;

#pragma unroll
        for (int kk = 0; kk < 32; kk += 16) {
            unsigned rb[4][2];
#pragma unroll
            for (int nt = 0; nt < 4; nt++) {
                const int r = wn * 32 + nt * 8 + g;
                rb[nt][0] = *(const unsigned*)&Bc[r * BST + kk + t2];
                rb[nt][1] = *(const unsigned*)&Bc[r * BST + kk + t2 + 8];
            }
#pragma unroll
            for (int mt = 0; mt < 4; mt++) {
                const int r = wm * 64 + mt * 16 + g;
                unsigned ra[4];
                ra[0] = *(const unsigned*)&Ac[r       * AST + kk + t2];
                ra[1] = *(const unsigned*)&Ac[(r + 8) * AST + kk + t2];
                ra[2] = *(const unsigned*)&Ac[r       * AST + kk + t2 + 8];
                ra[3] = *(const unsigned*)&Ac[(r + 8) * AST + kk + t2 + 8];
#pragma unroll
                for (int nt = 0; nt < 4; nt++)
                    mma16816(acc[mt][nt], ra, rb[nt]);
            }
        }
        __syncthreads();
    }

#pragma unroll
    for (int mt = 0; mt < 4; mt++) {
#pragma unroll
        for (int nt = 0; nt < 4; nt++) {
            const int row0 = m0 + wm * 64 + mt * 16 + g;
            const int col  = n0 + wn * 32 + nt * 8 + t2;
#pragma unroll
            for (int half = 0; half < 2; half++) {
                const int row = row0 + half * 8;
                float v0 = acc[mt][nt][half * 2 + 0];
                float v1 = acc[mt][nt][half * 2 + 1];
                if (bias)  { v0 += bias[col]; v1 += bias[col + 1]; }
                if (resid) { v0 += resid[(long)row * ldr + col];
                             v1 += resid[(long)row * ldr + col + 1]; }
                if (ACT == 1) {
                    v0 = 0.5f * v0 * (1.0f + erff(v0 * 0.70710678118654752f));
                    v1 = 0.5f * v1 * (1.0f + erff(v1 * 0.70710678118654752f));
                }
                if (OUTH) {
                    *(unsigned*)((__half*)Cv + (long)row * ldc + col) = packf2(v0, v1);
                } else {
                    float2 w; w.x = v0; w.y = v1;
                    *(float2*)((float*)Cv + (long)row * ldc + col) = w;
                }
            }
        }
    }
}

template<int ACT, bool OUTH>
__global__ void __launch_bounds__(256, 2)
mma_gemm(const __half* __restrict__ A, int lda,
         const __half* __restrict__ B, int ldb,
         void* __restrict__ Cv, int ldc,
         int K,
         const float* __restrict__ bias,
         const float* __restrict__ resid, int ldr)
{
    extern __shared__ __half smh[];
    gemm_body<ACT, OUTH>(A, lda, B, ldb, Cv, ldc, K,
                         blockIdx.y * 128, blockIdx.x * 128,
                         bias, resid, ldr, smh);
}

// two independent GEMMs (same M, K, lda/ldb) merged into one launch (tail fill)
__global__ void __launch_bounds__(256, 2)
mma_gemm_dual(const __half* __restrict__ A1, const __half* __restrict__ B1,
              __half* __restrict__ C1, int ldc1, int nx1,
              const __half* __restrict__ A2, const __half* __restrict__ B2,
              __half* __restrict__ C2, int ldc2,
              int lda, int K)
{
    extern __shared__ __half smh[];
    const int bx = blockIdx.x;
    if (bx < nx1) {
        gemm_body<0, true>(A1, lda, B1, lda, C1, ldc1, K,
                           blockIdx.y * 128, bx * 128,
                           nullptr, nullptr, 0, smh);
    } else {
        gemm_body<0, true>(A2, lda, B2, lda, C2, ldc2, K,
                           blockIdx.y * 128, (bx - nx1) * 128,
                           nullptr, nullptr, 0, smh);
    }
}

// ---------------- launcher ----------------
extern "C" void kernel_launch(void* const* d_in, const int* in_sizes, int n_in,
                              void* d_out, int out_size)
{
    const float* q     = (const float*)d_in[0];
    const float* kv    = (const float*)d_in[1];
    const float* n1g   = (const float*)d_in[2];
    const float* n1b   = (const float*)d_in[3];
    const float* qkv_w = (const float*)d_in[4];
    const float* sa_pw = (const float*)d_in[5];
    const float* sa_pb = (const float*)d_in[6];
    const float* n2qg  = (const float*)d_in[7];
    const float* n2qb  = (const float*)d_in[8];
    const float* n2kg  = (const float*)d_in[9];
    const float* n2kb  = (const float*)d_in[10];
    const float* caq_w = (const float*)d_in[11];
    const float* cakv_w= (const float*)d_in[12];
    const float* cap_w = (const float*)d_in[13];
    const float* cap_b = (const float*)d_in[14];
    const float* n3g   = (const float*)d_in[15];
    const float* n3b   = (const float*)d_in[16];
    const float* fc1w  = (const float*)d_in[17];
    const float* fc1b  = (const float*)d_in[18];
    const float* fc2w  = (const float*)d_in[19];
    const float* fc2b  = (const float*)d_in[20];
    float* out = (float*)d_out;

    __half *x, *xkv, *qkvb, *attn, *qh, *kvp, *hid;
    __half *wqkv, *wsa, *wcaq, *wcakv, *wcap, *wfc1, *wfc2;
    float *q1, *q2;
    cudaGetSymbolAddress((void**)&x,    g_x);
    cudaGetSymbolAddress((void**)&xkv,  g_xkv);
    cudaGetSymbolAddress((void**)&qkvb, g_qkv);
    cudaGetSymbolAddress((void**)&attn, g_attn);
    cudaGetSymbolAddress((void**)&qh,   g_qh);
    cudaGetSymbolAddress((void**)&kvp,  g_kvp);
    cudaGetSymbolAddress((void**)&q1,   g_q1);
    cudaGetSymbolAddress((void**)&q2,   g_q2);
    cudaGetSymbolAddress((void**)&hid,  g_hid);
    cudaGetSymbolAddress((void**)&wqkv, g_wqkv);
    cudaGetSymbolAddress((void**)&wsa,  g_wsa);
    cudaGetSymbolAddress((void**)&wcaq, g_wcaq);
    cudaGetSymbolAddress((void**)&wcakv,g_wcakv);
    cudaGetSymbolAddress((void**)&wcap, g_wcap);
    cudaGetSymbolAddress((void**)&wfc1, g_wfc1);
    cudaGetSymbolAddress((void**)&wfc2, g_wfc2);

    cudaFuncSetAttribute(mma_gemm<0,true>,
                         cudaFuncAttributeMaxDynamicSharedMemorySize, SM_MAIN);
    cudaFuncSetAttribute(mma_gemm<0,false>,
                         cudaFuncAttributeMaxDynamicSharedMemorySize, SM_MAIN);
    cudaFuncSetAttribute(mma_gemm<1,true>,
                         cudaFuncAttributeMaxDynamicSharedMemorySize, SM_MAIN);
    cudaFuncSetAttribute(mma_gemm_dual,
                         cudaFuncAttributeMaxDynamicSharedMemorySize, SM_MAIN);
    cudaFuncSetAttribute(flash_kernel,
                         cudaFuncAttributeMaxDynamicSharedMemorySize, FLASH_SMEM);

    const dim3 blk(256);
    const long QKV_B = (long)LQn * 3 * Dm;
    const long TOK_B = (long)LQn * Dm;
    const long KVP_B = (long)LKVn * 2 * Dm;

    // ---- weight conversion (merged) ----
    {
        CvtArgs a;
        a.s[0]=qkv_w;  a.d[0]=wqkv;  a.n[0]=3*Dm*Dm;
        a.s[1]=sa_pw;  a.d[1]=wsa;   a.n[1]=Dm*Dm;
        a.s[2]=caq_w;  a.d[2]=wcaq;  a.n[2]=Dm*Dm;
        a.s[3]=cakv_w; a.d[3]=wcakv; a.n[3]=2*Dm*Dm;
        a.s[4]=cap_w;  a.d[4]=wcap;  a.n[4]=Dm*Dm;
        a.s[5]=fc1w;   a.d[5]=wfc1;  a.n[5]=HIDn*Dm;
        a.s[6]=fc2w;   a.d[6]=wfc2;  a.n[6]=Dm*HIDn;
        cvt_all<<<dim3((HIDn*Dm + 255)/256, 7), 256>>>(a);
    }

    // ===== self-attention =====
    ln_kernel<<<NTOK/8, 256>>>(q, n1g, n1b, x);

    mma_gemm<0,true><<<dim3(3*Dm/128, NTOK/128), blk, SM_MAIN>>>(
        x, Dm, wqkv, Dm, qkvb, 3*Dm, Dm, nullptr, nullptr, 0);

    flash_kernel<<<dim3(LQn/128, Bq*Hn), blk, FLASH_SMEM>>>(
        qkvb,        3*Dm, QKV_B,
        qkvb + Dm,   3*Dm, QKV_B,
        qkvb + 2*Dm, 3*Dm, QKV_B,
        attn, Dm, TOK_B);

    mma_gemm<0,false><<<dim3(Dm/128, NTOK/128), blk, SM_MAIN>>>(
        attn, Dm, wsa, Dm, q1, Dm, Dm, sa_pb, q, Dm);

    // ===== cross-attention =====
    ln_kernel<<<NTOK/8, 256>>>(q1, n2qg, n2qb, x);
    ln_kernel<<<NTOK/8, 256>>>(kv, n2kg, n2kb, xkv);

    // merged ca_q + ca_kv projection (independent GEMMs, same M/K)
    mma_gemm_dual<<<dim3(Dm/128 + 2*Dm/128, NTOK/128), blk, SM_MAIN>>>(
        x,   wcaq,  qh,  Dm,   Dm/128,
        xkv, wcakv, kvp, 2*Dm,
        Dm, Dm);

    flash_kernel<<<dim3(LQn/128, Bq*Hn), blk, FLASH_SMEM>>>(
        qh,        Dm,   TOK_B,
        kvp,       2*Dm, KVP_B,
        kvp + Dm,  2*Dm, KVP_B,
        attn, Dm, TOK_B);

    mma_gemm<0,false><<<dim3(Dm/128, NTOK/128), blk, SM_MAIN>>>(
        attn, Dm, wcap, Dm, q2, Dm, Dm, cap_b, q1, Dm);

    // ===== MLP =====
    ln_kernel<<<NTOK/8, 256>>>(q2, n3g, n3b, x);

    mma_gemm<1,true><<<dim3(HIDn/128, NTOK/128), blk, SM_MAIN>>>(
        x, Dm, wfc1, Dm, hid, HIDn, Dm, fc1b, nullptr, 0);

    mma_gemm<0,false><<<dim3(Dm/128, NTOK/128), blk, SM_MAIN>>>(
        hid, HIDn, wfc2, HIDn, out, Dm, HIDn, fc2b, q2, Dm);
}

// round 14
// speedup vs baseline: 4.0182x; 1.0050x over previous
#include <cuda_runtime.h>
#include <cuda_fp16.h>
#include <math.h>

// ---------------- problem constants ----------------
#define Bq   16
#define LQn  512
#define LKVn 512
#define Dm   768
#define Hn   12
#define HDn  64
#define HIDn 3072
#define NTOK (Bq*LQn)          // 8192

// ---------------- scratch (device globals, plain fp16) ----------------
__device__ __align__(16) __half g_x   [NTOK*Dm];
__device__ __align__(16) __half g_xkv [NTOK*Dm];
__device__ __align__(16) __half g_qkv [NTOK*3*Dm];
__device__ __align__(16) __half g_attn[NTOK*Dm];
__device__ __align__(16) __half g_qh  [NTOK*Dm];
__device__ __align__(16) __half g_kvp [NTOK*2*Dm];
__device__ float  g_q1  [NTOK*Dm];
__device__ float  g_q2  [NTOK*Dm];
__device__ __align__(16) __half g_hid [NTOK*HIDn];
// converted weights
__device__ __align__(16) __half g_wqkv [3*Dm*Dm];
__device__ __align__(16) __half g_wsa  [Dm*Dm];
__device__ __align__(16) __half g_wcaq [Dm*Dm];
__device__ __align__(16) __half g_wcakv[2*Dm*Dm];
__device__ __align__(16) __half g_wcap [Dm*Dm];
__device__ __align__(16) __half g_wfc1 [HIDn*Dm];
__device__ __align__(16) __half g_wfc2 [Dm*HIDn];

// ---------------- helpers ----------------
__device__ __forceinline__ float warp_sum(float v){
#pragma unroll
    for (int o = 16; o > 0; o >>= 1) v += __shfl_xor_sync(0xffffffffu, v, o);
    return v;
}

__device__ __forceinline__ void mma16816(float* c, const unsigned* a, const unsigned* b){
    asm volatile(
        "mma.sync.aligned.m16n8k16.row.col.f32.f16.f16.f32 "
        "{%0,%1,%2,%3},{%4,%5,%6,%7},{%8,%9},{%0,%1,%2,%3};"
        : "+f"(c[0]), "+f"(c[1]), "+f"(c[2]), "+f"(c[3])
        : "r"(a[0]), "r"(a[1]), "r"(a[2]), "r"(a[3]), "r"(b[0]), "r"(b[1]));
}

__device__ __forceinline__ void cp16(void* smem_dst, const void* gsrc){
    unsigned s = (unsigned)__cvta_generic_to_shared(smem_dst);
    asm volatile("cp.async.cg.shared.global [%0], [%1], 16;\n" :: "r"(s), "l"(gsrc));
}
#define CP_COMMIT()  asm volatile("cp.async.commit_group;\n" ::: "memory")
#define CP_WAIT_1()  asm volatile("cp.async.wait_group 1;\n" ::: "memory")
#define CP_WAIT_0()  asm volatile("cp.async.wait_group 0;\n" ::: "memory")

// pack two fp32 into f16x2 register (low16 = p0)
__device__ __forceinline__ unsigned packf2(float p0, float p1){
    unsigned r;
    asm("cvt.rn.f16x2.f32 %0, %1, %2;" : "=r"(r) : "f"(p1), "f"(p0));
    return r;
}

// ---------------- merged weight conversion (blockIdx.y = segment) ----------------
struct CvtArgs {
    const float* s[7];
    __half*      d[7];
    int          n[7];
};
__global__ void cvt_all(CvtArgs a){
    const int seg = blockIdx.y;
    const int i = blockIdx.x * 256 + threadIdx.x;
    if (i < a.n[seg]) a.d[seg][i] = __float2half_rn(a.s[seg][i]);
}

// ---------------- LayerNorm, warp-per-row (no barriers) -> fp16 ----------------
__global__ void ln_kernel(const float* __restrict__ x, const float* __restrict__ g,
                          const float* __restrict__ b, __half* __restrict__ y)
{
    const int wid = threadIdx.x >> 5, lane = threadIdx.x & 31;
    const long row = (long)blockIdx.x * 8 + wid;
    const float* xr = x + row * Dm;

    float4 v[6];
    float s = 0.f;
#pragma unroll
    for (int i = 0; i < 6; i++) {
        v[i] = *(const float4*)(xr + i * 128 + lane * 4);
        s += v[i].x + v[i].y + v[i].z + v[i].w;
    }
    s = warp_sum(s);
    const float mean = s * (1.f / 768.f);

    float s2 = 0.f;
#pragma unroll
    for (int i = 0; i < 6; i++) {
        v[i].x -= mean; v[i].y -= mean; v[i].z -= mean; v[i].w -= mean;
        s2 += v[i].x*v[i].x + v[i].y*v[i].y + v[i].z*v[i].z + v[i].w*v[i].w;
    }
    s2 = warp_sum(s2);
    const float inv = rsqrtf(s2 * (1.f / 768.f) + 1e-5f);

    __half* yr = y + row * Dm;
#pragma unroll
    for (int i = 0; i < 6; i++) {
        const int c = i * 128 + lane * 4;
        float4 gg = *(const float4*)(g + c);
        float4 bb = *(const float4*)(b + c);
        uint2 w;
        w.x = packf2(v[i].x * inv * gg.x + bb.x, v[i].y * inv * gg.y + bb.y);
        w.y = packf2(v[i].z * inv * gg.z + bb.z, v[i].w * inv * gg.w + bb.w);
        *(uint2*)(yr + c) = w;
    }
}

// ---------------- fused flash attention (64 Q-rows / 128 threads, 2 CTAs/SM) ----------------
#define QS_ST 72
#define KS_ST 72
#define VS_ST 72
#define Q_TILE (64*QS_ST)    // halves
#define K_TILE (128*KS_ST)
#define V_TILE (128*VS_ST)
#define FLASH_SMEM ((Q_TILE + 2*K_TILE + 2*V_TILE) * 2)   // 82944 B

__global__ void __launch_bounds__(128, 2)
flash_kernel(const __half* __restrict__ Q, int ldq, long Qb,
             const __half* __restrict__ K, int ldk, long Kb,
             const __half* __restrict__ V, int ldv, long Vb,
             __half* __restrict__ O, int ldo, long Ob)
{
    extern __shared__ __half smh[];
    __half* Qs = smh;
    __half* Ks = smh + Q_TILE;
    __half* Vs = smh + Q_TILE + 2*K_TILE;

    const int tid  = threadIdx.x;
    const int wid  = tid >> 5, lane = tid & 31;
    const int g    = lane >> 2, t2 = (lane & 3) * 2;
    const int m0   = blockIdx.x * 64;
    const int wrow = wid * 16;

    {
        const int z = blockIdx.y;
        const int bb = z / Hn, hh = z - bb * Hn;
        Q += (long)bb * Qb + hh * 64;
        K += (long)bb * Kb + hh * 64;
        V += (long)bb * Vb + hh * 64;
        O += (long)bb * Ob + hh * 64;
    }

    auto loadQ = [&](){
#pragma unroll
        for (int idx = tid; idx < 512; idx += 128) {
            const int r = idx >> 3, c = idx & 7;
            cp16(&Qs[r * QS_ST + c * 8], Q + (long)(m0 + r) * ldq + c * 8);
        }
    };
    auto loadK = [&](int kt, int s){
        __half* dst = Ks + s * K_TILE;
#pragma unroll
        for (int idx = tid; idx < 1024; idx += 128) {
            const int r = idx >> 3, c = idx & 7;
            cp16(&dst[r * KS_ST + c * 8], K + (long)(kt * 128 + r) * ldk + c * 8);
        }
    };
    auto loadV = [&](int kt, int s){
        __half* dst = Vs + s * V_TILE;
#pragma unroll
        for (int idx = tid; idx < 1024; idx += 128) {
            const int r = idx >> 3, c = idx & 7;
            cp16(&dst[r * VS_ST + c * 8], V + (long)(kt * 128 + r) * ldv + c * 8);
        }
    };

    float o[8][4];
#pragma unroll
    for (int i = 0; i < 8; i++)
#pragma unroll
        for (int j = 0; j < 4; j++) o[i][j] = 0.f;
    float m_a = -1e30f, m_b = -1e30f, l_a = 0.f, l_b = 0.f;

    loadQ(); loadK(0, 0); loadV(0, 0); CP_COMMIT();
    loadK(1, 1); loadV(1, 1); CP_COMMIT();

    for (int it = 0; it < 4; it++) {
        if (it >= 1) {
            __syncthreads();
            if (it + 1 < 4) { loadK(it + 1, (it + 1) & 1); loadV(it + 1, (it + 1) & 1); CP_COMMIT(); }
        }
        if (it + 1 < 4) CP_WAIT_1(); else CP_WAIT_0();
        __syncthreads();

        const __half* Kc = Ks + (it & 1) * K_TILE;
        const __half* Vc = Vs + (it & 1) * V_TILE;

        // ---- S = Q K^T ----
        float s[16][4];
#pragma unroll
        for (int nt = 0; nt < 16; nt++)
#pragma unroll
            for (int c = 0; c < 4; c++) s[nt][c] = 0.f;

#pragma unroll
        for (int kk = 0; kk < 64; kk += 16) {
            const int r = wrow + g;
            unsigned ra[4];
            ra[0] = *(const unsigned*)&Qs[r       * QS_ST + kk + t2];
            ra[1] = *(const unsigned*)&Qs[(r + 8) * QS_ST + kk + t2];
            ra[2] = *(const unsigned*)&Qs[r       * QS_ST + kk + t2 + 8];
            ra[3] = *(const unsigned*)&Qs[(r + 8) * QS_ST + kk + t2 + 8];
#pragma unroll
            for (int nt = 0; nt < 16; nt++) {
                const int kr = nt * 8 + g;
                unsigned rb[2];
                rb[0] = *(const unsigned*)&Kc[kr * KS_ST + kk + t2];
                rb[1] = *(const unsigned*)&Kc[kr * KS_ST + kk + t2 + 8];
                mma16816(s[nt], ra, rb);
            }
        }

        // ---- online softmax (scale 1/8 folded) ----
        float mx_a = -1e30f, mx_b = -1e30f;
#pragma unroll
        for (int nt = 0; nt < 16; nt++) {
#pragma unroll
            for (int c = 0; c < 4; c++) s[nt][c] *= 0.125f;
            mx_a = fmaxf(mx_a, fmaxf(s[nt][0], s[nt][1]));
            mx_b = fmaxf(mx_b, fmaxf(s[nt][2], s[nt][3]));
        }
        mx_a = fmaxf(mx_a, __shfl_xor_sync(0xffffffffu, mx_a, 1));
        mx_a = fmaxf(mx_a, __shfl_xor_sync(0xffffffffu, mx_a, 2));
        mx_b = fmaxf(mx_b, __shfl_xor_sync(0xffffffffu, mx_b, 1));
        mx_b = fmaxf(mx_b, __shfl_xor_sync(0xffffffffu, mx_b, 2));

        const float nm_a = fmaxf(m_a, mx_a);
        const float nm_b = fmaxf(m_b, mx_b);
        const float sc_a = __expf(m_a - nm_a);
        const float sc_b = __expf(m_b - nm_b);
        m_a = nm_a; m_b = nm_b;
        l_a *= sc_a; l_b *= sc_b;
#pragma unroll
        for (int nt = 0; nt < 8; nt++) {
            o[nt][0] *= sc_a; o[nt][1] *= sc_a;
            o[nt][2] *= sc_b; o[nt][3] *= sc_b;
        }
        float sum_a = 0.f, sum_b = 0.f;
#pragma unroll
        for (int nt = 0; nt < 16; nt++) {
            s[nt][0] = __expf(s[nt][0] - nm_a);
            s[nt][1] = __expf(s[nt][1] - nm_a);
            s[nt][2] = __expf(s[nt][2] - nm_b);
            s[nt][3] = __expf(s[nt][3] - nm_b);
            sum_a += s[nt][0] + s[nt][1];
            sum_b += s[nt][2] + s[nt][3];
        }
        l_a += sum_a; l_b += sum_b;

        // ---- O += P V ----
        const unsigned short* Vu = (const unsigned short*)Vc;
#pragma unroll
        for (int ks = 0; ks < 8; ks++) {
            unsigned ra[4];
            ra[0] = packf2(s[2*ks  ][0], s[2*ks  ][1]);
            ra[1] = packf2(s[2*ks  ][2], s[2*ks  ][3]);
            ra[2] = packf2(s[2*ks+1][0], s[2*ks+1][1]);
            ra[3] = packf2(s[2*ks+1][2], s[2*ks+1][3]);
            const int r0 = ks * 16 + t2;
#pragma unroll
            for (int nt = 0; nt < 8; nt++) {
                const int n = nt * 8 + g;
                unsigned b0 = (unsigned)Vu[(r0    ) * VS_ST + n]
                            | ((unsigned)Vu[(r0 + 1) * VS_ST + n] << 16);
                unsigned b1 = (unsigned)Vu[(r0 + 8) * VS_ST + n]
                            | ((unsigned)Vu[(r0 + 9) * VS_ST + n] << 16);
                unsigned rb[2] = {b0, b1};
                mma16816(o[nt], ra, rb);
            }
        }
    }

    l_a += __shfl_xor_sync(0xffffffffu, l_a, 1);
    l_a += __shfl_xor_sync(0xffffffffu, l_a, 2);
    l_b += __shfl_xor_sync(0xffffffffu, l_b, 1);
    l_b += __shfl_xor_sync(0xffffffffu, l_b, 2);
    const float inv_a = 1.f / l_a;
    const float inv_b = 1.f / l_b;

    const int row_a = m0 + wrow + g;
    const int row_b = row_a + 8;
#pragma unroll
    for (int nt = 0; nt < 8; nt++) {
        const int col = nt * 8 + t2;
        *(unsigned*)&O[(long)row_a * ldo + col] = packf2(o[nt][0] * inv_a, o[nt][1] * inv_a);
        *(unsigned*)&O[(long)row_b * ldo + col] = packf2(o[nt][2] * inv_b, o[nt][3] * inv_b);
    }
}

// ---------------- GEMM core (shared by single and dual variants) ----------------
#define AST  40
#define BST  40
#define A_TILE_H (128*AST)
#define B_TILE_H (128*BST)
#define STAGE_H  (A_TILE_H + B_TILE_H)
#define SM_MAIN  (STAGE_H * 2 * 2)     // 40960 B

template<int ACT, bool OUTH>
__device__ __forceinline__ void gemm_body(
    const __half* __restrict__ A, int lda,
    const __half* __restrict__ B, int ldb,
    void* __restrict__ Cv, int ldc,
    int K, int m0, int n0,
    const float* __restrict__ bias,
    const float* __restrict__ resid, int ldr,
    __half* smh)
{
    const int tid = threadIdx.x;
    const int wid = tid >> 5, lane = tid & 31;
    const int wm = wid >> 2, wn = wid & 3;            // 2x4 warp grid, 64x32 tiles
    const int g  = lane >> 2, t2 = (lane & 3) * 2;

    float acc[4][4][4];
#pragma unroll
    for (int i = 0; i < 4; i++)
#pragma unroll
        for (int j = 0; j < 4; j++)
#pragma unroll
            for (int c = 0; c < 4; c++) acc[i][j][c] = 0.f;

    auto load_tiles = [&](int k0, int s){
        __half* Ad = smh + s * STAGE_H;
        __half* Bd = Ad + A_TILE_H;
#pragma unroll
        for (int idx = tid; idx < 512; idx += 256) {
            const int r = idx >> 2, c = idx & 3;
            cp16(&Ad[r * AST + c * 8], A + (long)(m0 + r) * lda + k0 + c * 8);
        }
#pragma unroll
        for (int idx = tid; idx < 512; idx += 256) {
            const int r = idx >> 2, c = idx & 3;
            cp16(&Bd[r * BST + c * 8], B + (long)(n0 + r) * ldb + k0 + c * 8);
        }
    };

    const int iters = K / 32;
    load_tiles(0, 0);
    CP_COMMIT();

    for (int it = 0; it < iters; it++) {
        if (it + 1 < iters) {
            load_tiles((it + 1) * 32, (it + 1) & 1);
            CP_COMMIT();
            CP_WAIT_1();
        } else {
            CP_WAIT_0();
        }
        __syncthreads();

        const __half* Ac = smh + (it & 1) * STAGE_H;
        const __half* Bc = Ac + A_TILE_H;

#pragma unroll
        for (int kk = 0; kk < 32; kk += 16) {
            unsigned rb[4][2];
#pragma unroll
            for (int nt = 0; nt < 4; nt++) {
                const int r = wn * 32 + nt * 8 + g;
                rb[nt][0] = *(const unsigned*)&Bc[r * BST + kk + t2];
                rb[nt][1] = *(const unsigned*)&Bc[r * BST + kk + t2 + 8];
            }
#pragma unroll
            for (int mt = 0; mt < 4; mt++) {
                const int r = wm * 64 + mt * 16 + g;
                unsigned ra[4];
                ra[0] = *(const unsigned*)&Ac[r       * AST + kk + t2];
                ra[1] = *(const unsigned*)&Ac[(r + 8) * AST + kk + t2];
                ra[2] = *(const unsigned*)&Ac[r       * AST + kk + t2 + 8];
                ra[3] = *(const unsigned*)&Ac[(r + 8) * AST + kk + t2 + 8];
#pragma unroll
                for (int nt = 0; nt < 4; nt++)
                    mma16816(acc[mt][nt], ra, rb[nt]);
            }
        }
        __syncthreads();
    }

#pragma unroll
    for (int mt = 0; mt < 4; mt++) {
#pragma unroll
        for (int nt = 0; nt < 4; nt++) {
            const int row0 = m0 + wm * 64 + mt * 16 + g;
            const int col  = n0 + wn * 32 + nt * 8 + t2;
#pragma unroll
            for (int half = 0; half < 2; half++) {
                const int row = row0 + half * 8;
                float v0 = acc[mt][nt][half * 2 + 0];
                float v1 = acc[mt][nt][half * 2 + 1];
                if (bias)  { v0 += bias[col]; v1 += bias[col + 1]; }
                if (resid) { v0 += resid[(long)row * ldr + col];
                             v1 += resid[(long)row * ldr + col + 1]; }
                if (ACT == 1) {
                    v0 = 0.5f * v0 * (1.0f + erff(v0 * 0.70710678118654752f));
                    v1 = 0.5f * v1 * (1.0f + erff(v1 * 0.70710678118654752f));
                }
                if (OUTH) {
                    *(unsigned*)((__half*)Cv + (long)row * ldc + col) = packf2(v0, v1);
                } else {
                    float2 w; w.x = v0; w.y = v1;
                    *(float2*)((float*)Cv + (long)row * ldc + col) = w;
                }
            }
        }
    }
}

template<int ACT, bool OUTH>
__global__ void __launch_bounds__(256, 2)
mma_gemm(const __half* __restrict__ A, int lda,
         const __half* __restrict__ B, int ldb,
         void* __restrict__ Cv, int ldc,
         int K,
         const float* __restrict__ bias,
         const float* __restrict__ resid, int ldr)
{
    extern __shared__ __half smh[];
    gemm_body<ACT, OUTH>(A, lda, B, ldb, Cv, ldc, K,
                         blockIdx.y * 128, blockIdx.x * 128,
                         bias, resid, ldr, smh);
}

// two independent GEMMs (same M, K, lda/ldb) merged into one launch
__global__ void __launch_bounds__(256, 2)
mma_gemm_dual(const __half* __restrict__ A1, const __half* __restrict__ B1,
              __half* __restrict__ C1, int ldc1, int nx1,
              const __half* __restrict__ A2, const __half* __restrict__ B2,
              __half* __restrict__ C2, int ldc2,
              int lda, int K)
{
    extern __shared__ __half smh[];
    const int bx = blockIdx.x;
    if (bx < nx1) {
        gemm_body<0, true>(A1, lda, B1, lda, C1, ldc1, K,
                           blockIdx.y * 128, bx * 128,
                           nullptr, nullptr, 0, smh);
    } else {
        gemm_body<0, true>(A2, lda, B2, lda, C2, ldc2, K,
                           blockIdx.y * 128, (bx - nx1) * 128,
                           nullptr, nullptr, 0, smh);
    }
}

// ---------------- launcher ----------------
extern "C" void kernel_launch(void* const* d_in, const int* in_sizes, int n_in,
                              void* d_out, int out_size)
{
    const float* q     = (const float*)d_in[0];
    const float* kv    = (const float*)d_in[1];
    const float* n1g   = (const float*)d_in[2];
    const float* n1b   = (const float*)d_in[3];
    const float* qkv_w = (const float*)d_in[4];
    const float* sa_pw = (const float*)d_in[5];
    const float* sa_pb = (const float*)d_in[6];
    const float* n2qg  = (const float*)d_in[7];
    const float* n2qb  = (const float*)d_in[8];
    const float* n2kg  = (const float*)d_in[9];
    const float* n2kb  = (const float*)d_in[10];
    const float* caq_w = (const float*)d_in[11];
    const float* cakv_w= (const float*)d_in[12];
    const float* cap_w = (const float*)d_in[13];
    const float* cap_b = (const float*)d_in[14];
    const float* n3g   = (const float*)d_in[15];
    const float* n3b   = (const float*)d_in[16];
    const float* fc1w  = (const float*)d_in[17];
    const float* fc1b  = (const float*)d_in[18];
    const float* fc2w  = (const float*)d_in[19];
    const float* fc2b  = (const float*)d_in[20];
    float* out = (float*)d_out;

    __half *x, *xkv, *qkvb, *attn, *qh, *kvp, *hid;
    __half *wqkv, *wsa, *wcaq, *wcakv, *wcap, *wfc1, *wfc2;
    float *q1, *q2;
    cudaGetSymbolAddress((void**)&x,    g_x);
    cudaGetSymbolAddress((void**)&xkv,  g_xkv);
    cudaGetSymbolAddress((void**)&qkvb, g_qkv);
    cudaGetSymbolAddress((void**)&attn, g_attn);
    cudaGetSymbolAddress((void**)&qh,   g_qh);
    cudaGetSymbolAddress((void**)&kvp,  g_kvp);
    cudaGetSymbolAddress((void**)&q1,   g_q1);
    cudaGetSymbolAddress((void**)&q2,   g_q2);
    cudaGetSymbolAddress((void**)&hid,  g_hid);
    cudaGetSymbolAddress((void**)&wqkv, g_wqkv);
    cudaGetSymbolAddress((void**)&wsa,  g_wsa);
    cudaGetSymbolAddress((void**)&wcaq, g_wcaq);
    cudaGetSymbolAddress((void**)&wcakv,g_wcakv);
    cudaGetSymbolAddress((void**)&wcap, g_wcap);
    cudaGetSymbolAddress((void**)&wfc1, g_wfc1);
    cudaGetSymbolAddress((void**)&wfc2, g_wfc2);

    cudaFuncSetAttribute(mma_gemm<0,true>,
                         cudaFuncAttributeMaxDynamicSharedMemorySize, SM_MAIN);
    cudaFuncSetAttribute(mma_gemm<0,false>,
                         cudaFuncAttributeMaxDynamicSharedMemorySize, SM_MAIN);
    cudaFuncSetAttribute(mma_gemm<1,true>,
                         cudaFuncAttributeMaxDynamicSharedMemorySize, SM_MAIN);
    cudaFuncSetAttribute(mma_gemm_dual,
                         cudaFuncAttributeMaxDynamicSharedMemorySize, SM_MAIN);
    cudaFuncSetAttribute(flash_kernel,
                         cudaFuncAttributeMaxDynamicSharedMemorySize, FLASH_SMEM);

    const dim3 blk(256);
    const long QKV_B = (long)LQn * 3 * Dm;
    const long TOK_B = (long)LQn * Dm;
    const long KVP_B = (long)LKVn * 2 * Dm;

    // ---- weight conversion (merged) ----
    {
        CvtArgs a;
        a.s[0]=qkv_w;  a.d[0]=wqkv;  a.n[0]=3*Dm*Dm;
        a.s[1]=sa_pw;  a.d[1]=wsa;   a.n[1]=Dm*Dm;
        a.s[2]=caq_w;  a.d[2]=wcaq;  a.n[2]=Dm*Dm;
        a.s[3]=cakv_w; a.d[3]=wcakv; a.n[3]=2*Dm*Dm;
        a.s[4]=cap_w;  a.d[4]=wcap;  a.n[4]=Dm*Dm;
        a.s[5]=fc1w;   a.d[5]=wfc1;  a.n[5]=HIDn*Dm;
        a.s[6]=fc2w;   a.d[6]=wfc2;  a.n[6]=Dm*HIDn;
        cvt_all<<<dim3((HIDn*Dm + 255)/256, 7), 256>>>(a);
    }

    // ===== LNs for both attention inputs =====
    ln_kernel<<<NTOK/8, 256>>>(q, n1g, n1b, x);
    ln_kernel<<<NTOK/8, 256>>>(kv, n2kg, n2kb, xkv);

    // ===== merged qkv + ca_kv projections (independent, same M/K) =====
    mma_gemm_dual<<<dim3(3*Dm/128 + 2*Dm/128, NTOK/128), blk, SM_MAIN>>>(
        x,   wqkv,  qkvb, 3*Dm, 3*Dm/128,
        xkv, wcakv, kvp,  2*Dm,
        Dm, Dm);

    // ===== self-attention =====
    flash_kernel<<<dim3(LQn/64, Bq*Hn), 128, FLASH_SMEM>>>(
        qkvb,        3*Dm, QKV_B,
        qkvb + Dm,   3*Dm, QKV_B,
        qkvb + 2*Dm, 3*Dm, QKV_B,
        attn, Dm, TOK_B);

    mma_gemm<0,false><<<dim3(Dm/128, NTOK/128), blk, SM_MAIN>>>(
        attn, Dm, wsa, Dm, q1, Dm, Dm, sa_pb, q, Dm);

    // ===== cross-attention =====
    ln_kernel<<<NTOK/8, 256>>>(q1, n2qg, n2qb, x);

    mma_gemm<0,true><<<dim3(Dm/128, NTOK/128), blk, SM_MAIN>>>(
        x, Dm, wcaq, Dm, qh, Dm, Dm, nullptr, nullptr, 0);

    flash_kernel<<<dim3(LQn/64, Bq*Hn), 128, FLASH_SMEM>>>(
        qh,        Dm,   TOK_B,
        kvp,       2*Dm, KVP_B,
        kvp + Dm,  2*Dm, KVP_B,
        attn, Dm, TOK_B);

    mma_gemm<0,false><<<dim3(Dm/128, NTOK/128), blk, SM_MAIN>>>(
        attn, Dm, wcap, Dm, q2, Dm, Dm, cap_b, q1, Dm);

    // ===== MLP =====
    ln_kernel<<<NTOK/8, 256>>>(q2, n3g, n3b, x);

    mma_gemm<1,true><<<dim3(HIDn/128, NTOK/128), blk, SM_MAIN>>>(
        x, Dm, wfc1, Dm, hid, HIDn, Dm, fc1b, nullptr, 0);

    mma_gemm<0,false><<<dim3(Dm/128, NTOK/128), blk, SM_MAIN>>>(
        hid, HIDn, wfc2, HIDn, out, Dm, HIDn, fc2b, q2, Dm);
}

// round 15
// speedup vs baseline: 4.7818x; 1.1900x over previous
#include <cuda_runtime.h>
#include <cuda_fp16.h>
#include <math.h>

// ---------------- problem constants ----------------
#define Bq   16
#define LQn  512
#define LKVn 512
#define Dm   768
#define Hn   12
#define HDn  64
#define HIDn 3072
#define NTOK (Bq*LQn)          // 8192

// ---------------- scratch (device globals, plain fp16) ----------------
__device__ __align__(16) __half g_x   [NTOK*Dm];
__device__ __align__(16) __half g_xkv [NTOK*Dm];
__device__ __align__(16) __half g_qkv [NTOK*3*Dm];
__device__ __align__(16) __half g_attn[NTOK*Dm];
__device__ __align__(16) __half g_qh  [NTOK*Dm];
__device__ __align__(16) __half g_kvp [NTOK*2*Dm];
__device__ float  g_q1  [NTOK*Dm];
__device__ float  g_q2  [NTOK*Dm];
__device__ __align__(16) __half g_hid [NTOK*HIDn];
// converted weights
__device__ __align__(16) __half g_wqkv [3*Dm*Dm];
__device__ __align__(16) __half g_wsa  [Dm*Dm];
__device__ __align__(16) __half g_wcaq [Dm*Dm];
__device__ __align__(16) __half g_wcakv[2*Dm*Dm];
__device__ __align__(16) __half g_wcap [Dm*Dm];
__device__ __align__(16) __half g_wfc1 [HIDn*Dm];
__device__ __align__(16) __half g_wfc2 [Dm*HIDn];

// ---------------- helpers ----------------
__device__ __forceinline__ float warp_sum(float v){
#pragma unroll
    for (int o = 16; o > 0; o >>= 1) v += __shfl_xor_sync(0xffffffffu, v, o);
    return v;
}

__device__ __forceinline__ void mma16816(float* c, const unsigned* a, const unsigned* b){
    asm volatile(
        "mma.sync.aligned.m16n8k16.row.col.f32.f16.f16.f32 "
        "{%0,%1,%2,%3},{%4,%5,%6,%7},{%8,%9},{%0,%1,%2,%3};"
        : "+f"(c[0]), "+f"(c[1]), "+f"(c[2]), "+f"(c[3])
        : "r"(a[0]), "r"(a[1]), "r"(a[2]), "r"(a[3]), "r"(b[0]), "r"(b[1]));
}

__device__ __forceinline__ void cp16(void* smem_dst, const void* gsrc){
    unsigned s = (unsigned)__cvta_generic_to_shared(smem_dst);
    asm volatile("cp.async.cg.shared.global [%0], [%1], 16;\n" :: "r"(s), "l"(gsrc));
}
#define CP_COMMIT()  asm volatile("cp.async.commit_group;\n" ::: "memory")
#define CP_WAIT_1()  asm volatile("cp.async.wait_group 1;\n" ::: "memory")
#define CP_WAIT_0()  asm volatile("cp.async.wait_group 0;\n" ::: "memory")

__device__ __forceinline__ void ldsm4(unsigned& r0, unsigned& r1, unsigned& r2, unsigned& r3,
                                      unsigned addr){
    asm volatile("ldmatrix.sync.aligned.m8n8.x4.shared.b16 {%0,%1,%2,%3}, [%4];"
        : "=r"(r0), "=r"(r1), "=r"(r2), "=r"(r3) : "r"(addr));
}

// pack two fp32 into f16x2 register (low16 = p0)
__device__ __forceinline__ unsigned packf2(float p0, float p1){
    unsigned r;
    asm("cvt.rn.f16x2.f32 %0, %1, %2;" : "=r"(r) : "f"(p1), "f"(p0));
    return r;
}

// ---------------- merged weight conversion (blockIdx.y = segment) ----------------
struct CvtArgs {
    const float* s[7];
    __half*      d[7];
    int          n[7];
};
__global__ void cvt_all(CvtArgs a){
    const int seg = blockIdx.y;
    const int i = blockIdx.x * 256 + threadIdx.x;
    if (i < a.n[seg]) a.d[seg][i] = __float2half_rn(a.s[seg][i]);
}

// ---------------- LayerNorm, warp-per-row (no barriers) -> fp16 ----------------
__global__ void ln_kernel(const float* __restrict__ x, const float* __restrict__ g,
                          const float* __restrict__ b, __half* __restrict__ y)
{
    const int wid = threadIdx.x >> 5, lane = threadIdx.x & 31;
    const long row = (long)blockIdx.x * 8 + wid;
    const float* xr = x + row * Dm;

    float4 v[6];
    float s = 0.f;
#pragma unroll
    for (int i = 0; i < 6; i++) {
        v[i] = *(const float4*)(xr + i * 128 + lane * 4);
        s += v[i].x + v[i].y + v[i].z + v[i].w;
    }
    s = warp_sum(s);
    const float mean = s * (1.f / 768.f);

    float s2 = 0.f;
#pragma unroll
    for (int i = 0; i < 6; i++) {
        v[i].x -= mean; v[i].y -= mean; v[i].z -= mean; v[i].w -= mean;
        s2 += v[i].x*v[i].x + v[i].y*v[i].y + v[i].z*v[i].z + v[i].w*v[i].w;
    }
    s2 = warp_sum(s2);
    const float inv = rsqrtf(s2 * (1.f / 768.f) + 1e-5f);

    __half* yr = y + row * Dm;
#pragma unroll
    for (int i = 0; i < 6; i++) {
        const int c = i * 128 + lane * 4;
        float4 gg = *(const float4*)(g + c);
        float4 bb = *(const float4*)(b + c);
        uint2 w;
        w.x = packf2(v[i].x * inv * gg.x + bb.x, v[i].y * inv * gg.y + bb.y);
        w.y = packf2(v[i].z * inv * gg.z + bb.z, v[i].w * inv * gg.w + bb.w);
        *(uint2*)(yr + c) = w;
    }
}

// ---------------- fused flash attention (64 Q-rows / 128 threads, 2 CTAs/SM) ----------------
#define QS_ST 72
#define KS_ST 72
#define VS_ST 72
#define Q_TILE (64*QS_ST)    // halves
#define K_TILE (128*KS_ST)
#define V_TILE (128*VS_ST)
#define FLASH_SMEM ((Q_TILE + 2*K_TILE + 2*V_TILE) * 2)   // 82944 B

__global__ void __launch_bounds__(128, 2)
flash_kernel(const __half* __restrict__ Q, int ldq, long Qb,
             const __half* __restrict__ K, int ldk, long Kb,
             const __half* __restrict__ V, int ldv, long Vb,
             __half* __restrict__ O, int ldo, long Ob)
{
    extern __shared__ __half smh[];
    __half* Qs = smh;
    __half* Ks = smh + Q_TILE;
    __half* Vs = smh + Q_TILE + 2*K_TILE;

    const int tid  = threadIdx.x;
    const int wid  = tid >> 5, lane = tid & 31;
    const int g    = lane >> 2, t2 = (lane & 3) * 2;
    const int m0   = blockIdx.x * 64;
    const int wrow = wid * 16;

    {
        const int z = blockIdx.y;
        const int bb = z / Hn, hh = z - bb * Hn;
        Q += (long)bb * Qb + hh * 64;
        K += (long)bb * Kb + hh * 64;
        V += (long)bb * Vb + hh * 64;
        O += (long)bb * Ob + hh * 64;
    }

    auto loadQ = [&](){
#pragma unroll
        for (int idx = tid; idx < 512; idx += 128) {
            const int r = idx >> 3, c = idx & 7;
            cp16(&Qs[r * QS_ST + c * 8], Q + (long)(m0 + r) * ldq + c * 8);
        }
    };
    auto loadK = [&](int kt, int s){
        __half* dst = Ks + s * K_TILE;
#pragma unroll
        for (int idx = tid; idx < 1024; idx += 128) {
            const int r = idx >> 3, c = idx & 7;
            cp16(&dst[r * KS_ST + c * 8], K + (long)(kt * 128 + r) * ldk + c * 8);
        }
    };
    auto loadV = [&](int kt, int s){
        __half* dst = Vs + s * V_TILE;
#pragma unroll
        for (int idx = tid; idx < 1024; idx += 128) {
            const int r = idx >> 3, c = idx & 7;
            cp16(&dst[r * VS_ST + c * 8], V + (long)(kt * 128 + r) * ldv + c * 8);
        }
    };

    float o[8][4];
#pragma unroll
    for (int i = 0; i < 8; i++)
#pragma unroll
        for (int j = 0; j < 4; j++) o[i][j] = 0.f;
    float m_a = -1e30f, m_b = -1e30f, l_a = 0.f, l_b = 0.f;

    loadQ(); loadK(0, 0); loadV(0, 0); CP_COMMIT();
    loadK(1, 1); loadV(1, 1); CP_COMMIT();

    for (int it = 0; it < 4; it++) {
        if (it >= 1) {
            __syncthreads();
            if (it + 1 < 4) { loadK(it + 1, (it + 1) & 1); loadV(it + 1, (it + 1) & 1); CP_COMMIT(); }
        }
        if (it + 1 < 4) CP_WAIT_1(); else CP_WAIT_0();
        __syncthreads();

        const __half* Kc = Ks + (it & 1) * K_TILE;
        const __half* Vc = Vs + (it & 1) * V_TILE;

        // ---- S = Q K^T ----
        float s[16][4];
#pragma unroll
        for (int nt = 0; nt < 16; nt++)
#pragma unroll
            for (int c = 0; c < 4; c++) s[nt][c] = 0.f;

#pragma unroll
        for (int kk = 0; kk < 64; kk += 16) {
            const int r = wrow + g;
            unsigned ra[4];
            ra[0] = *(const unsigned*)&Qs[r       * QS_ST + kk + t2];
            ra[1] = *(const unsigned*)&Qs[(r + 8) * QS_ST + kk + t2];
            ra[2] = *(const unsigned*)&Qs[r       * QS_ST + kk + t2 + 8];
            ra[3] = *(const unsigned*)&Qs[(r + 8) * QS_ST + kk + t2 + 8];
#pragma unroll
            for (int nt = 0; nt < 16; nt++) {
                const int kr = nt * 8 + g;
                unsigned rb[2];
                rb[0] = *(const unsigned*)&Kc[kr * KS_ST + kk + t2];
                rb[1] = *(const unsigned*)&Kc[kr * KS_ST + kk + t2 + 8];
                mma16816(s[nt], ra, rb);
            }
        }

        // ---- online softmax (scale 1/8 folded) ----
        float mx_a = -1e30f, mx_b = -1e30f;
#pragma unroll
        for (int nt = 0; nt < 16; nt++) {
#pragma unroll
            for (int c = 0; c < 4; c++) s[nt][c] *= 0.125f;
            mx_a = fmaxf(mx_a, fmaxf(s[nt][0], s[nt][1]));
            mx_b = fmaxf(mx_b, fmaxf(s[nt][2], s[nt][3]));
        }
        mx_a = fmaxf(mx_a, __shfl_xor_sync(0xffffffffu, mx_a, 1));
        mx_a = fmaxf(mx_a, __shfl_xor_sync(0xffffffffu, mx_a, 2));
        mx_b = fmaxf(mx_b, __shfl_xor_sync(0xffffffffu, mx_b, 1));
        mx_b = fmaxf(mx_b, __shfl_xor_sync(0xffffffffu, mx_b, 2));

        const float nm_a = fmaxf(m_a, mx_a);
        const float nm_b = fmaxf(m_b, mx_b);
        const float sc_a = __expf(m_a - nm_a);
        const float sc_b = __expf(m_b - nm_b);
        m_a = nm_a; m_b = nm_b;
        l_a *= sc_a; l_b *= sc_b;
#pragma unroll
        for (int nt = 0; nt < 8; nt++) {
            o[nt][0] *= sc_a; o[nt][1] *= sc_a;
            o[nt][2] *= sc_b; o[nt][3] *= sc_b;
        }
        float sum_a = 0.f, sum_b = 0.f;
#pragma unroll
        for (int nt = 0; nt < 16; nt++) {
            s[nt][0] = __expf(s[nt][0] - nm_a);
            s[nt][1] = __expf(s[nt][1] - nm_a);
            s[nt][2] = __expf(s[nt][2] - nm_b);
            s[nt][3] = __expf(s[nt][3] - nm_b);
            sum_a += s[nt][0] + s[nt][1];
            sum_b += s[nt][2] + s[nt][3];
        }
        l_a += sum_a; l_b += sum_b;

        // ---- O += P V ----
        const unsigned short* Vu = (const unsigned short*)Vc;
#pragma unroll
        for (int ks = 0; ks < 8; ks++) {
            unsigned ra[4];
            ra[0] = packf2(s[2*ks  ][0], s[2*ks  ][1]);
            ra[1] = packf2(s[2*ks  ][2], s[2*ks  ][3]);
            ra[2] = packf2(s[2*ks+1][0], s[2*ks+1][1]);
            ra[3] = packf2(s[2*ks+1][2], s[2*ks+1][3]);
            const int r0 = ks * 16 + t2;
#pragma unroll
            for (int nt = 0; nt < 8; nt++) {
                const int n = nt * 8 + g;
                unsigned b0 = (unsigned)Vu[(r0    ) * VS_ST + n]
                            | ((unsigned)Vu[(r0 + 1) * VS_ST + n] << 16);
                unsigned b1 = (unsigned)Vu[(r0 + 8) * VS_ST + n]
                            | ((unsigned)Vu[(r0 + 9) * VS_ST + n] << 16);
                unsigned rb[2] = {b0, b1};
                mma16816(o[nt], ra, rb);
            }
        }
    }

    l_a += __shfl_xor_sync(0xffffffffu, l_a, 1);
    l_a += __shfl_xor_sync(0xffffffffu, l_a, 2);
    l_b += __shfl_xor_sync(0xffffffffu, l_b, 1);
    l_b += __shfl_xor_sync(0xffffffffu, l_b, 2);
    const float inv_a = 1.f / l_a;
    const float inv_b = 1.f / l_b;

    const int row_a = m0 + wrow + g;
    const int row_b = row_a + 8;
#pragma unroll
    for (int nt = 0; nt < 8; nt++) {
        const int col = nt * 8 + t2;
        *(unsigned*)&O[(long)row_a * ldo + col] = packf2(o[nt][0] * inv_a, o[nt][1] * inv_a);
        *(unsigned*)&O[(long)row_b * ldo + col] = packf2(o[nt][2] * inv_b, o[nt][3] * inv_b);
    }
}

// ---------------- GEMM core: BK=64, ldmatrix fragments, 2-stage, 2 CTAs/SM ----------------
#define AST  72                         // halves per row (144 B): conflict-free LDSM phases
#define A_TILE_H (128*AST)              // 9216 halves
#define STAGE_H  (2*A_TILE_H)           // A + B
#define SM_MAIN  (STAGE_H * 2 * 2)      // 73728 B (2 stages)

template<int ACT, bool OUTH>
__device__ __forceinline__ void gemm_body(
    const __half* __restrict__ A, int lda,
    const __half* __restrict__ B, int ldb,
    void* __restrict__ Cv, int ldc,
    int K, int m0, int n0,
    const float* __restrict__ bias,
    const float* __restrict__ resid, int ldr,
    __half* smh)
{
    const int tid = threadIdx.x;
    const int wid = tid >> 5, lane = tid & 31;
    const int wm = wid >> 2, wn = wid & 3;            // 2x4 warp grid, 64x32 tiles
    const int g  = lane >> 2, t2 = (lane & 3) * 2;
    const int l8 = lane & 7, q = lane >> 3;

    const unsigned smb = (unsigned)__cvta_generic_to_shared(smh);
    // ldmatrix per-thread base addresses (bytes, stage 0)
    const int rowA = (q & 1) * 8 + l8, colA = (q >> 1) * 8;
    const int rowB = (q >> 1) * 8 + l8, colB = (q & 1) * 8;
    const unsigned aA = smb + ((wm*64 + rowA) * AST + colA) * 2;
    const unsigned aB = smb + A_TILE_H * 2 + ((wn*32 + rowB) * AST + colB) * 2;

    float acc[4][4][4];
#pragma unroll
    for (int i = 0; i < 4; i++)
#pragma unroll
        for (int j = 0; j < 4; j++)
#pragma unroll
            for (int c = 0; c < 4; c++) acc[i][j][c] = 0.f;

    auto load_tiles = [&](int k0, int s){
        __half* Ad = smh + s * STAGE_H;
        __half* Bd = Ad + A_TILE_H;
#pragma unroll
        for (int idx = tid; idx < 1024; idx += 256) {
            const int r = idx >> 3, c = idx & 7;
            cp16(&Ad[r * AST + c * 8], A + (long)(m0 + r) * lda + k0 + c * 8);
        }
#pragma unroll
        for (int idx = tid; idx < 1024; idx += 256) {
            const int r = idx >> 3, c = idx & 7;
            cp16(&Bd[r * AST + c * 8], B + (long)(n0 + r) * ldb + k0 + c * 8);
        }
    };

    const int iters = K / 64;
    load_tiles(0, 0);
    CP_COMMIT();

    for (int it = 0; it < iters; it++) {
        if (it + 1 < iters) {
            load_tiles((it + 1) * 64, (it + 1) & 1);
            CP_COMMIT();
            CP_WAIT_1();
        } else {
            CP_WAIT_0();
        }
        __syncthreads();

        const unsigned so = (it & 1) * (STAGE_H * 2);   // byte offset

#pragma unroll
        for (int kk = 0; kk < 64; kk += 16) {
            const unsigned ko = so + kk * 2;
            unsigned rb[4][2];
            ldsm4(rb[0][0], rb[0][1], rb[1][0], rb[1][1], aB + ko);
            ldsm4(rb[2][0], rb[2][1], rb[3][0], rb[3][1], aB + ko + 16 * AST * 2);
#pragma unroll
            for (int mt = 0; mt < 4; mt++) {
                unsigned ra[4];
                ldsm4(ra[0], ra[1], ra[2], ra[3], aA + ko + mt * 16 * AST * 2);
#pragma unroll
                for (int nt = 0; nt < 4; nt++)
                    mma16816(acc[mt][nt], ra, rb[nt]);
            }
        }
        __syncthreads();
    }

#pragma unroll
    for (int mt = 0; mt < 4; mt++) {
#pragma unroll
        for (int nt = 0; nt < 4; nt++) {
            const int row0 = m0 + wm * 64 + mt * 16 + g;
            const int col  = n0 + wn * 32 + nt * 8 + t2;
#pragma unroll
            for (int half = 0; half < 2; half++) {
                const int row = row0 + half * 8;
                float v0 = acc[mt][nt][half * 2 + 0];
                float v1 = acc[mt][nt][half * 2 + 1];
                if (bias)  { v0 += bias[col]; v1 += bias[col + 1]; }
                if (resid) { v0 += resid[(long)row * ldr + col];
                             v1 += resid[(long)row * ldr + col + 1]; }
                if (ACT == 1) {
                    v0 = 0.5f * v0 * (1.0f + erff(v0 * 0.70710678118654752f));
                    v1 = 0.5f * v1 * (1.0f + erff(v1 * 0.70710678118654752f));
                }
                if (OUTH) {
                    *(unsigned*)((__half*)Cv + (long)row * ldc + col) = packf2(v0, v1);
                } else {
                    float2 w; w.x = v0; w.y = v1;
                    *(float2*)((float*)Cv + (long)row * ldc + col) = w;
                }
            }
        }
    }
}

template<int ACT, bool OUTH>
__global__ void __launch_bounds__(256, 2)
mma_gemm(const __half* __restrict__ A, int lda,
         const __half* __restrict__ B, int ldb,
         void* __restrict__ Cv, int ldc,
         int K,
         const float* __restrict__ bias,
         const float* __restrict__ resid, int ldr)
{
    extern __shared__ __half smh[];
    gemm_body<ACT, OUTH>(A, lda, B, ldb, Cv, ldc, K,
                         blockIdx.y * 128, blockIdx.x * 128,
                         bias, resid, ldr, smh);
}

// two independent GEMMs (same M, K, lda/ldb) merged into one launch
__global__ void __launch_bounds__(256, 2)
mma_gemm_dual(const __half* __restrict__ A1, const __half* __restrict__ B1,
              __half* __restrict__ C1, int ldc1, int nx1,
              const __half* __restrict__ A2, const __half* __restrict__ B2,
              __half* __restrict__ C2, int ldc2,
              int lda, int K)
{
    extern __shared__ __half smh[];
    const int bx = blockIdx.x;
    if (bx < nx1) {
        gemm_body<0, true>(A1, lda, B1, lda, C1, ldc1, K,
                           blockIdx.y * 128, bx * 128,
                           nullptr, nullptr, 0, smh);
    } else {
        gemm_body<0, true>(A2, lda, B2, lda, C2, ldc2, K,
                           blockIdx.y * 128, (bx - nx1) * 128,
                           nullptr, nullptr, 0, smh);
    }
}

// ---------------- launcher ----------------
extern "C" void kernel_launch(void* const* d_in, const int* in_sizes, int n_in,
                              void* d_out, int out_size)
{
    const float* q     = (const float*)d_in[0];
    const float* kv    = (const float*)d_in[1];
    const float* n1g   = (const float*)d_in[2];
    const float* n1b   = (const float*)d_in[3];
    const float* qkv_w = (const float*)d_in[4];
    const float* sa_pw = (const float*)d_in[5];
    const float* sa_pb = (const float*)d_in[6];
    const float* n2qg  = (const float*)d_in[7];
    const float* n2qb  = (const float*)d_in[8];
    const float* n2kg  = (const float*)d_in[9];
    const float* n2kb  = (const float*)d_in[10];
    const float* caq_w = (const float*)d_in[11];
    const float* cakv_w= (const float*)d_in[12];
    const float* cap_w = (const float*)d_in[13];
    const float* cap_b = (const float*)d_in[14];
    const float* n3g   = (const float*)d_in[15];
    const float* n3b   = (const float*)d_in[16];
    const float* fc1w  = (const float*)d_in[17];
    const float* fc1b  = (const float*)d_in[18];
    const float* fc2w  = (const float*)d_in[19];
    const float* fc2b  = (const float*)d_in[20];
    float* out = (float*)d_out;

    __half *x, *xkv, *qkvb, *attn, *qh, *kvp, *hid;
    __half *wqkv, *wsa, *wcaq, *wcakv, *wcap, *wfc1, *wfc2;
    float *q1, *q2;
    cudaGetSymbolAddress((void**)&x,    g_x);
    cudaGetSymbolAddress((void**)&xkv,  g_xkv);
    cudaGetSymbolAddress((void**)&qkvb, g_qkv);
    cudaGetSymbolAddress((void**)&attn, g_attn);
    cudaGetSymbolAddress((void**)&qh,   g_qh);
    cudaGetSymbolAddress((void**)&kvp,  g_kvp);
    cudaGetSymbolAddress((void**)&q1,   g_q1);
    cudaGetSymbolAddress((void**)&q2,   g_q2);
    cudaGetSymbolAddress((void**)&hid,  g_hid);
    cudaGetSymbolAddress((void**)&wqkv, g_wqkv);
    cudaGetSymbolAddress((void**)&wsa,  g_wsa);
    cudaGetSymbolAddress((void**)&wcaq, g_wcaq);
    cudaGetSymbolAddress((void**)&wcakv,g_wcakv);
    cudaGetSymbolAddress((void**)&wcap, g_wcap);
    cudaGetSymbolAddress((void**)&wfc1, g_wfc1);
    cudaGetSymbolAddress((void**)&wfc2, g_wfc2);

    cudaFuncSetAttribute(mma_gemm<0,true>,
                         cudaFuncAttributeMaxDynamicSharedMemorySize, SM_MAIN);
    cudaFuncSetAttribute(mma_gemm<0,false>,
                         cudaFuncAttributeMaxDynamicSharedMemorySize, SM_MAIN);
    cudaFuncSetAttribute(mma_gemm<1,true>,
                         cudaFuncAttributeMaxDynamicSharedMemorySize, SM_MAIN);
    cudaFuncSetAttribute(mma_gemm_dual,
                         cudaFuncAttributeMaxDynamicSharedMemorySize, SM_MAIN);
    cudaFuncSetAttribute(flash_kernel,
                         cudaFuncAttributeMaxDynamicSharedMemorySize, FLASH_SMEM);

    const dim3 blk(256);
    const long QKV_B = (long)LQn * 3 * Dm;
    const long TOK_B = (long)LQn * Dm;
    const long KVP_B = (long)LKVn * 2 * Dm;

    // ---- weight conversion (merged) ----
    {
        CvtArgs a;
        a.s[0]=qkv_w;  a.d[0]=wqkv;  a.n[0]=3*Dm*Dm;
        a.s[1]=sa_pw;  a.d[1]=wsa;   a.n[1]=Dm*Dm;
        a.s[2]=caq_w;  a.d[2]=wcaq;  a.n[2]=Dm*Dm;
        a.s[3]=cakv_w; a.d[3]=wcakv; a.n[3]=2*Dm*Dm;
        a.s[4]=cap_w;  a.d[4]=wcap;  a.n[4]=Dm*Dm;
        a.s[5]=fc1w;   a.d[5]=wfc1;  a.n[5]=HIDn*Dm;
        a.s[6]=fc2w;   a.d[6]=wfc2;  a.n[6]=Dm*HIDn;
        cvt_all<<<dim3((HIDn*Dm + 255)/256, 7), 256>>>(a);
    }

    // ===== LNs for both attention inputs =====
    ln_kernel<<<NTOK/8, 256>>>(q, n1g, n1b, x);
    ln_kernel<<<NTOK/8, 256>>>(kv, n2kg, n2kb, xkv);

    // ===== merged qkv + ca_kv projections (independent, same M/K) =====
    mma_gemm_dual<<<dim3(3*Dm/128 + 2*Dm/128, NTOK/128), blk, SM_MAIN>>>(
        x,   wqkv,  qkvb, 3*Dm, 3*Dm/128,
        xkv, wcakv, kvp,  2*Dm,
        Dm, Dm);

    // ===== self-attention =====
    flash_kernel<<<dim3(LQn/64, Bq*Hn), 128, FLASH_SMEM>>>(
        qkvb,        3*Dm, QKV_B,
        qkvb + Dm,   3*Dm, QKV_B,
        qkvb + 2*Dm, 3*Dm, QKV_B,
        attn, Dm, TOK_B);

    mma_gemm<0,false><<<dim3(Dm/128, NTOK/128), blk, SM_MAIN>>>(
        attn, Dm, wsa, Dm, q1, Dm, Dm, sa_pb, q, Dm);

    // ===== cross-attention =====
    ln_kernel<<<NTOK/8, 256>>>(q1, n2qg, n2qb, x);

    mma_gemm<0,true><<<dim3(Dm/128, NTOK/128), blk, SM_MAIN>>>(
        x, Dm, wcaq, Dm, qh, Dm, Dm, nullptr, nullptr, 0);

    flash_kernel<<<dim3(LQn/64, Bq*Hn), 128, FLASH_SMEM>>>(
        qh,        Dm,   TOK_B,
        kvp,       2*Dm, KVP_B,
        kvp + Dm,  2*Dm, KVP_B,
        attn, Dm, TOK_B);

    mma_gemm<0,false><<<dim3(Dm/128, NTOK/128), blk, SM_MAIN>>>(
        attn, Dm, wcap, Dm, q2, Dm, Dm, cap_b, q1, Dm);

    // ===== MLP =====
    ln_kernel<<<NTOK/8, 256>>>(q2, n3g, n3b, x);

    mma_gemm<1,true><<<dim3(HIDn/128, NTOK/128), blk, SM_MAIN>>>(
        x, Dm, wfc1, Dm, hid, HIDn, Dm, fc1b, nullptr, 0);

    mma_gemm<0,false><<<dim3(Dm/128, NTOK/128), blk, SM_MAIN>>>(
        hid, HIDn, wfc2, HIDn, out, Dm, HIDn, fc2b, q2, Dm);
}